// round 1
// baseline (speedup 1.0000x reference)
#include <cuda_runtime.h>
#include <math.h>

#define Nn 65536
#define Ee 262144
#define Kk 8
#define NMPc 2
#define DEPTHc 2
#define Hh 4
#define Dd 256
#define PHp 64
#define EDd 64

// -------- scratch (device globals; no allocation allowed) --------
__device__ float g_dummy[Nn * Dd];
__device__ float g_base [Nn * Dd];
__device__ float g_x    [Nn * Dd];
__device__ float g_eA   [(size_t)Ee * Dd];
__device__ float g_eB   [(size_t)Ee * Dd];
__device__ float g_pn   [Nn * Hh];
__device__ float g_be   [Ee * Hh];
__device__ float g_ps   [Nn * Hh];
__device__ float g_qe   [Ee * Hh];

// -------- generic 64x64 tiled fp32 GEMM: C[M,Ncols] = A[M,Kd] @ B[Kd,Ncols] --------
__global__ __launch_bounds__(256) void gemm64(const float* __restrict__ A,
                                              const float* __restrict__ B,
                                              float* __restrict__ C,
                                              int M, int Kd, int Ncols)
{
    __shared__ float As[16][65];
    __shared__ float Bs[16][64];
    int t  = threadIdx.x;
    int tx = t & 15, ty = t >> 4;
    int m0 = blockIdx.y * 64;
    int n0 = blockIdx.x * 64;
    float acc[4][4] = {};
    for (int k0 = 0; k0 < Kd; k0 += 16) {
        int kk = t & 15;
        int rb = t >> 4;
        #pragma unroll
        for (int p = 0; p < 4; p++) {
            int r = rb + p * 16;
            As[kk][r] = A[(size_t)(m0 + r) * Kd + k0 + kk];
        }
        #pragma unroll
        for (int p = 0; p < 4; p++) {
            int kr  = (t >> 6) + p * 4;
            int col = t & 63;
            Bs[kr][col] = B[(size_t)(k0 + kr) * Ncols + n0 + col];
        }
        __syncthreads();
        #pragma unroll
        for (int q = 0; q < 16; q++) {
            float a[4], b[4];
            #pragma unroll
            for (int i = 0; i < 4; i++) a[i] = As[q][ty * 4 + i];
            #pragma unroll
            for (int j = 0; j < 4; j++) b[j] = Bs[q][tx * 4 + j];
            #pragma unroll
            for (int i = 0; i < 4; i++)
                #pragma unroll
                for (int j = 0; j < 4; j++) acc[i][j] += a[i] * b[j];
        }
        __syncthreads();
    }
    #pragma unroll
    for (int i = 0; i < 4; i++)
        #pragma unroll
        for (int j = 0; j < 4; j++)
            C[(size_t)(m0 + ty * 4 + i) * Ncols + n0 + tx * 4 + j] = acc[i][j];
}

// -------- row-dot: P[m,h] = dot(avec[h,:], X[m,:]) , D=256 fixed --------
__global__ __launch_bounds__(256) void rowdot(const float* __restrict__ X,
                                              const float* __restrict__ avec,
                                              float* __restrict__ P, int M)
{
    __shared__ float sa[Hh * Dd];
    int t = threadIdx.x;
    for (int i = t; i < Hh * Dd; i += 256) sa[i] = avec[i];
    __syncthreads();
    int row  = blockIdx.x * 8 + (t >> 5);
    int lane = t & 31;
    const float* xr = X + (size_t)row * Dd;
    float acc[Hh] = {};
    #pragma unroll
    for (int j = 0; j < 8; j++) {
        float xv = xr[lane + 32 * j];
        #pragma unroll
        for (int h = 0; h < Hh; h++) acc[h] += sa[h * Dd + lane + 32 * j] * xv;
    }
    #pragma unroll
    for (int h = 0; h < Hh; h++) {
        #pragma unroll
        for (int o = 16; o > 0; o >>= 1) acc[h] += __shfl_down_sync(0xffffffffu, acc[h], o);
    }
    if (lane == 0) {
        #pragma unroll
        for (int h = 0; h < Hh; h++) P[(size_t)row * Hh + h] = acc[h];
    }
}

// -------- fused edge aggregator: attention(q=2) + agg + (edges+agg)@W_e + ELU --------
// Block: 64 edges x all 256 output cols (4 heads x 64)
__global__ __launch_bounds__(256) void edge_out(const float* __restrict__ x,
                                                const float* __restrict__ edges,
                                                const int* __restrict__ ena,
                                                const float* __restrict__ pn,
                                                const float* __restrict__ be,
                                                const float* __restrict__ W,  // [H,D,PH]
                                                float* __restrict__ eout)
{
    __shared__ float al0[Hh][64], al1[Hh][64];
    __shared__ int   su[64], sv[64];
    __shared__ float As[Hh][64][17];
    __shared__ float Bs[16][256];
    int t  = threadIdx.x;
    int e0 = blockIdx.x * 64;
    if (t < 64) {
        int e = e0 + t;
        int u = ena[2 * e], v = ena[2 * e + 1];
        su[t] = u; sv[t] = v;
        #pragma unroll
        for (int h = 0; h < Hh; h++) {
            float b  = be[(size_t)e * Hh + h];
            float s0 = pn[(size_t)u * Hh + h] + b;
            float s1 = pn[(size_t)v * Hh + h] + b;
            s0 = s0 > 0.f ? s0 : 0.2f * s0;
            s1 = s1 > 0.f ? s1 : 0.2f * s1;
            float m  = fmaxf(s0, s1);
            float x0 = __expf(s0 - m), x1 = __expf(s1 - m);
            float inv = 1.f / (x0 + x1);
            al0[h][t] = x0 * inv; al1[h][t] = x1 * inv;
        }
    }
    __syncthreads();
    int tx = t & 15, ty = t >> 4;
    int h  = tx >> 2;  // cols tx*16..tx*16+15 all belong to head tx/4
    float acc[4][16] = {};
    for (int k0 = 0; k0 < Dd; k0 += 16) {
        #pragma unroll
        for (int p = 0; p < 4; p++) {
            int idx = p * 256 + t;
            int er = idx >> 4, kk = idx & 15;
            int k = k0 + kk;
            float ed = edges[(size_t)(e0 + er) * Dd + k];
            float xu = x[(size_t)su[er] * Dd + k];
            float xv = x[(size_t)sv[er] * Dd + k];
            #pragma unroll
            for (int hh = 0; hh < Hh; hh++)
                As[hh][er][kk] = ed + al0[hh][er] * xu + al1[hh][er] * xv;
        }
        #pragma unroll
        for (int p = 0; p < 16; p++)
            Bs[p][t] = W[(size_t)(t >> 6) * Dd * PHp + (size_t)(k0 + p) * PHp + (t & 63)];
        __syncthreads();
        #pragma unroll
        for (int q = 0; q < 16; q++) {
            float a[4];
            #pragma unroll
            for (int i = 0; i < 4; i++) a[i] = As[h][ty * 4 + i][q];
            #pragma unroll
            for (int c = 0; c < 16; c++) {
                float bb = Bs[q][tx * 16 + c];
                #pragma unroll
                for (int i = 0; i < 4; i++) acc[i][c] += a[i] * bb;
            }
        }
        __syncthreads();
    }
    #pragma unroll
    for (int i = 0; i < 4; i++) {
        size_t row = (size_t)(e0 + ty * 4 + i);
        #pragma unroll
        for (int c = 0; c < 16; c++) {
            float v2 = acc[i][c];
            v2 = v2 > 0.f ? v2 : expm1f(v2);
            eout[row * Dd + tx * 16 + c] = v2;
        }
    }
}

// -------- fused node aggregator: attention(K=8) + nag + xin@Wself + nag@Wnb + ELU --------
__global__ __launch_bounds__(256) void node_out(const float* __restrict__ xin,
                                                const float* __restrict__ edges,
                                                const int* __restrict__ n2e,
                                                const float* __restrict__ ps,
                                                const float* __restrict__ qe,
                                                const float* __restrict__ Wself, // [H,D,PH]
                                                const float* __restrict__ Wnb,   // [H,D,PH]
                                                float* __restrict__ xout,
                                                float* __restrict__ out,
                                                int Lofs, int writeX)
{
    __shared__ float aln[Hh][64][Kk];
    __shared__ int   sidx[64][Kk];
    __shared__ float AsS[64][9];
    __shared__ float AsN[Hh][64][9];
    __shared__ float BsS[8][256];
    __shared__ float BsN[8][256];
    int t  = threadIdx.x;
    int n0 = blockIdx.x * 64;
    if (t < 64) {
        int n = n0 + t;
        int idxs[Kk];
        #pragma unroll
        for (int k = 0; k < Kk; k++) { idxs[k] = n2e[(size_t)n * Kk + k]; sidx[t][k] = idxs[k]; }
        #pragma unroll
        for (int h = 0; h < Hh; h++) {
            float bs = ps[(size_t)n * Hh + h];
            float s[Kk]; float m = -1e30f;
            #pragma unroll
            for (int k = 0; k < Kk; k++) {
                float sv = bs + qe[(size_t)idxs[k] * Hh + h];
                sv = sv > 0.f ? sv : 0.2f * sv;
                s[k] = sv; m = fmaxf(m, sv);
            }
            float sum = 0.f;
            #pragma unroll
            for (int k = 0; k < Kk; k++) { s[k] = __expf(s[k] - m); sum += s[k]; }
            float inv = 1.f / sum;
            #pragma unroll
            for (int k = 0; k < Kk; k++) aln[h][t][k] = s[k] * inv;
        }
    }
    __syncthreads();
    int tx = t & 15, ty = t >> 4;
    int h  = tx >> 2;
    float acc[4][16] = {};
    for (int k0 = 0; k0 < Dd; k0 += 8) {
        #pragma unroll
        for (int p = 0; p < 2; p++) {
            int idx = p * 256 + t;
            int r = idx >> 3, kk = idx & 7;
            AsS[r][kk] = xin[(size_t)(n0 + r) * Dd + k0 + kk];
            float a4[Hh] = {0.f, 0.f, 0.f, 0.f};
            #pragma unroll
            for (int k = 0; k < Kk; k++) {
                float ev = edges[(size_t)sidx[r][k] * Dd + k0 + kk];
                #pragma unroll
                for (int hh = 0; hh < Hh; hh++) a4[hh] += aln[hh][r][k] * ev;
            }
            #pragma unroll
            for (int hh = 0; hh < Hh; hh++) AsN[hh][r][kk] = a4[hh];
        }
        #pragma unroll
        for (int p = 0; p < 8; p++) {
            size_t widx = (size_t)(t >> 6) * Dd * PHp + (size_t)(k0 + p) * PHp + (t & 63);
            BsS[p][t] = Wself[widx];
            BsN[p][t] = Wnb[widx];
        }
        __syncthreads();
        #pragma unroll
        for (int q = 0; q < 8; q++) {
            float as_[4], an_[4];
            #pragma unroll
            for (int i = 0; i < 4; i++) { as_[i] = AsS[ty * 4 + i][q]; an_[i] = AsN[h][ty * 4 + i][q]; }
            #pragma unroll
            for (int c = 0; c < 16; c++) {
                float bs_ = BsS[q][tx * 16 + c], bn_ = BsN[q][tx * 16 + c];
                #pragma unroll
                for (int i = 0; i < 4; i++) acc[i][c] += as_[i] * bs_ + an_[i] * bn_;
            }
        }
        __syncthreads();
    }
    #pragma unroll
    for (int i = 0; i < 4; i++) {
        int n = n0 + ty * 4 + i;
        #pragma unroll
        for (int c = 0; c < 16; c++) {
            float v2 = acc[i][c];
            v2 = v2 > 0.f ? v2 : expm1f(v2);
            int col = tx * 16 + c;
            out[(size_t)n * (DEPTHc * Dd) + Lofs + col] = v2;
            if (writeX) xout[(size_t)n * Dd + col] = v2;
        }
    }
}

extern "C" void kernel_launch(void* const* d_in, const int* in_sizes, int n_in,
                              void* d_out, int out_size)
{
    (void)in_sizes; (void)n_in; (void)out_size;
    const float* feats    = (const float*)d_in[0];
    const float* edge_emb = (const float*)d_in[1];
    const int*   ena      = (const int*)d_in[2];
    const int*   n2e      = (const int*)d_in[3];
    const float* Wp0      = (const float*)d_in[4];
    const float* Wp1      = (const float*)d_in[5];
    const float* Wep      = (const float*)d_in[6];
    const float* a_e      = (const float*)d_in[7];
    const float* a_n      = (const float*)d_in[8];
    const float* W_e      = (const float*)d_in[9];
    const float* a_s      = (const float*)d_in[10];
    const float* a_edge   = (const float*)d_in[11];
    const float* W_self   = (const float*)d_in[12];
    const float* W_nb     = (const float*)d_in[13];
    float* out = (float*)d_out;

    float *dummy, *base, *xb, *eA, *eB, *pn, *be, *ps, *qe;
    cudaGetSymbolAddress((void**)&dummy, g_dummy);
    cudaGetSymbolAddress((void**)&base,  g_base);
    cudaGetSymbolAddress((void**)&xb,    g_x);
    cudaGetSymbolAddress((void**)&eA,    g_eA);
    cudaGetSymbolAddress((void**)&eB,    g_eB);
    cudaGetSymbolAddress((void**)&pn,    g_pn);
    cudaGetSymbolAddress((void**)&be,    g_be);
    cudaGetSymbolAddress((void**)&ps,    g_ps);
    cudaGetSymbolAddress((void**)&qe,    g_qe);

    dim3 blk(256);
    // prep: dummy = feats @ W_prep0 ; base = feats @ W_prep1
    gemm64<<<dim3(Dd / 64, Nn / 64), blk>>>(feats, Wp0, dummy, Nn, Dd, Dd);
    gemm64<<<dim3(Dd / 64, Nn / 64), blk>>>(feats, Wp1, base, Nn, Dd, Dd);

    for (int mp = 0; mp < NMPc; mp++) {
        // edges = edge_emb[mp] @ W_eprep[mp]
        gemm64<<<dim3(Dd / 64, Ee / 64), blk>>>(edge_emb + (size_t)mp * Ee * EDd,
                                                Wep + (size_t)mp * EDd * Dd,
                                                eA, Ee, EDd, Dd);
        const int* ena_mp = ena + (size_t)mp * Ee * 2;
        const int* n2e_mp = n2e + (size_t)mp * Nn * Kk;
        float* outmp = out + (size_t)mp * Nn * DEPTHc * Dd;

        // ---- layer 0 ----
        size_t pl0 = (size_t)(mp * DEPTHc + 0);
        rowdot<<<Nn / 8, blk>>>(base, a_n + pl0 * Hh * Dd, pn, Nn);
        rowdot<<<Ee / 8, blk>>>(eA,   a_e + pl0 * Hh * Dd, be, Ee);
        edge_out<<<Ee / 64, blk>>>(base, eA, ena_mp, pn, be,
                                   W_e + pl0 * Hh * Dd * PHp, eB);
        rowdot<<<Nn / 8, blk>>>(dummy, a_s    + pl0 * Hh * Dd, ps, Nn);
        rowdot<<<Ee / 8, blk>>>(eA,    a_edge + pl0 * Hh * Dd, qe, Ee);
        node_out<<<Nn / 64, blk>>>(dummy, eA, n2e_mp, ps, qe,
                                   W_self + pl0 * Hh * Dd * PHp,
                                   W_nb   + pl0 * Hh * Dd * PHp,
                                   xb, outmp, 0, 1);

        // ---- layer 1 (edge aggregator output is never consumed -> skipped) ----
        size_t pl1 = (size_t)(mp * DEPTHc + 1);
        rowdot<<<Nn / 8, blk>>>(xb, a_s    + pl1 * Hh * Dd, ps, Nn);
        rowdot<<<Ee / 8, blk>>>(eB, a_edge + pl1 * Hh * Dd, qe, Ee);
        node_out<<<Nn / 64, blk>>>(xb, eB, n2e_mp, ps, qe,
                                   W_self + pl1 * Hh * Dd * PHp,
                                   W_nb   + pl1 * Hh * Dd * PHp,
                                   xb, outmp, Dd, 0);
    }
}

// round 3
// speedup vs baseline: 2.8793x; 2.8793x over previous
#include <cuda_runtime.h>
#include <cuda_bf16.h>
#include <math.h>
#include <stdint.h>

#define Nn 65536
#define Ee 262144
#define Kk 8
#define NMPc 2
#define DEPTHc 2
#define Hh 4
#define Dd 256
#define PHp 64
#define EDd 64

// ---------------- scratch (device globals; no allocation allowed) ----------------
__device__ float g_dummy[(size_t)Nn * Dd];
__device__ float g_base [(size_t)Nn * Dd];
__device__ float g_x    [(size_t)Nn * Dd];
__device__ float g_Y    [(size_t)Nn * Dd];
__device__ float g_S    [(size_t)Nn * Dd];
__device__ float g_NP   [(size_t)Nn * Dd];
__device__ float g_eA   [(size_t)Ee * Dd];
__device__ float g_eB   [(size_t)Ee * Dd];
__device__ float g_EW   [(size_t)Ee * Dd];
__device__ float g_nag  [(size_t)Hh * Nn * Dd];
__device__ float g_pn   [(size_t)Nn * Hh];
__device__ float g_be   [(size_t)Ee * Hh];
__device__ float g_ps   [(size_t)Nn * Hh];
__device__ float g_qe   [(size_t)Ee * Hh];
__device__ float g_Bt0  [Dd * Dd];
__device__ float g_Bt1  [Dd * Dd];
__device__ float g_Bt2  [Dd * Dd];

// ---------------- HMMA helper ----------------
__device__ __forceinline__ void mma16816(float* c, const uint32_t* a, uint32_t b0, uint32_t b1) {
    asm volatile("mma.sync.aligned.m16n8k16.row.col.f32.bf16.bf16.f32 "
                 "{%0,%1,%2,%3}, {%4,%5,%6,%7}, {%8,%9}, {%0,%1,%2,%3};"
                 : "+f"(c[0]), "+f"(c[1]), "+f"(c[2]), "+f"(c[3])
                 : "r"(a[0]), "r"(a[1]), "r"(a[2]), "r"(a[3]), "r"(b0), "r"(b1));
}

__device__ __forceinline__ void split4(float4 v, uint2& hi, uint2& lo) {
    __nv_bfloat16 h0 = __float2bfloat16(v.x), h1 = __float2bfloat16(v.y);
    __nv_bfloat16 h2 = __float2bfloat16(v.z), h3 = __float2bfloat16(v.w);
    __nv_bfloat16 l0 = __float2bfloat16(v.x - __bfloat162float(h0));
    __nv_bfloat16 l1 = __float2bfloat16(v.y - __bfloat162float(h1));
    __nv_bfloat16 l2 = __float2bfloat16(v.z - __bfloat162float(h2));
    __nv_bfloat16 l3 = __float2bfloat16(v.w - __bfloat162float(h3));
    union { __nv_bfloat162 b[2]; uint2 u; } ph, pl;
    ph.b[0] = __nv_bfloat162(h0, h1); ph.b[1] = __nv_bfloat162(h2, h3);
    pl.b[0] = __nv_bfloat162(l0, l1); pl.b[1] = __nv_bfloat162(l2, l3);
    hi = ph.u; lo = pl.u;
}

// ---------------- bf16-split HMMA GEMM: C[M, gridDim.y*BN] = A[M,K] @ Bt[*,K]^T ----------------
// Block tile: 128(M) x BN(N), K-chunk 32. 8 warps = 4(M) x 2(N).
// 3 MMAs per tile: Ah*Bh + Al*Bh + Ah*Bl  (error ~2^-16 relative).
template <int BN>
__global__ __launch_bounds__(256) void gemm_mma(const float* __restrict__ A,
                                                const float* __restrict__ Bt,
                                                float* __restrict__ C,
                                                int K, int ldc)
{
    constexpr int NT = BN / 16;          // n8-tiles per warp
    __shared__ uint16_t sAh[128][40], sAl[128][40];
    __shared__ uint16_t sBh[BN][40],  sBl[BN][40];

    int t = threadIdx.x, wid = t >> 5, lane = t & 31;
    int g = lane >> 2, tg = lane & 3;
    int wm = (wid >> 1) * 32;
    int wn = (wid & 1) * (BN / 2);
    size_t m0 = (size_t)blockIdx.x * 128;
    size_t n0 = (size_t)blockIdx.y * BN;

    float acc[2][NT][4];
    #pragma unroll
    for (int mt = 0; mt < 2; mt++)
        #pragma unroll
        for (int nt = 0; nt < NT; nt++)
            #pragma unroll
            for (int j = 0; j < 4; j++) acc[mt][nt][j] = 0.f;

    int nkb = K >> 5;
    for (int kb = 0; kb < nkb; kb++) {
        // stage A chunk (128 x 32 fp32 -> bf16 hi/lo)
        const float* Ab = A + m0 * K + kb * 32;
        #pragma unroll
        for (int i = 0; i < 4; i++) {
            int id = t + 256 * i;
            int r = id >> 3, c4 = id & 7;
            float4 v = *(const float4*)(Ab + (size_t)r * K + c4 * 4);
            uint2 hi, lo; split4(v, hi, lo);
            *(uint2*)&sAh[r][c4 * 4] = hi;
            *(uint2*)&sAl[r][c4 * 4] = lo;
        }
        // stage B chunk (BN x 32)
        const float* Bb = Bt + n0 * K + kb * 32;
        #pragma unroll
        for (int i = 0; i < BN / 32; i++) {
            int id = t + 256 * i;
            int r = id >> 3, c4 = id & 7;
            float4 v = *(const float4*)(Bb + (size_t)r * K + c4 * 4);
            uint2 hi, lo; split4(v, hi, lo);
            *(uint2*)&sBh[r][c4 * 4] = hi;
            *(uint2*)&sBl[r][c4 * 4] = lo;
        }
        __syncthreads();
        #pragma unroll
        for (int ks = 0; ks < 2; ks++) {
            int kc = ks * 16 + tg * 2;
            uint32_t ah[2][4], al_[2][4];
            #pragma unroll
            for (int mt = 0; mt < 2; mt++) {
                int row = wm + mt * 16 + g;
                ah[mt][0]  = *(const uint32_t*)&sAh[row][kc];
                ah[mt][1]  = *(const uint32_t*)&sAh[row + 8][kc];
                ah[mt][2]  = *(const uint32_t*)&sAh[row][kc + 8];
                ah[mt][3]  = *(const uint32_t*)&sAh[row + 8][kc + 8];
                al_[mt][0] = *(const uint32_t*)&sAl[row][kc];
                al_[mt][1] = *(const uint32_t*)&sAl[row + 8][kc];
                al_[mt][2] = *(const uint32_t*)&sAl[row][kc + 8];
                al_[mt][3] = *(const uint32_t*)&sAl[row + 8][kc + 8];
            }
            #pragma unroll
            for (int nt = 0; nt < NT; nt++) {
                int col = wn + nt * 8 + g;
                uint32_t bh0 = *(const uint32_t*)&sBh[col][kc];
                uint32_t bh1 = *(const uint32_t*)&sBh[col][kc + 8];
                uint32_t bl0 = *(const uint32_t*)&sBl[col][kc];
                uint32_t bl1 = *(const uint32_t*)&sBl[col][kc + 8];
                #pragma unroll
                for (int mt = 0; mt < 2; mt++) {
                    mma16816(acc[mt][nt], ah[mt],  bh0, bh1);
                    mma16816(acc[mt][nt], al_[mt], bh0, bh1);
                    mma16816(acc[mt][nt], ah[mt],  bl0, bl1);
                }
            }
        }
        __syncthreads();
    }
    // epilogue: direct f32 stores (c0,c1 are a contiguous col pair)
    #pragma unroll
    for (int mt = 0; mt < 2; mt++) {
        size_t row = m0 + wm + mt * 16 + g;
        #pragma unroll
        for (int nt = 0; nt < NT; nt++) {
            size_t col = n0 + wn + nt * 8 + tg * 2;
            *(float2*)(C + row * ldc + col)       = make_float2(acc[mt][nt][0], acc[mt][nt][1]);
            *(float2*)(C + (row + 8) * ldc + col) = make_float2(acc[mt][nt][2], acc[mt][nt][3]);
        }
    }
}

// ---------------- weight packing ----------------
__global__ void pack2d(const float* __restrict__ src, float* __restrict__ dst, int Kd, int Cc) {
    int id = blockIdx.x * 256 + threadIdx.x;
    if (id < Kd * Cc) { int c = id % Cc, k = id / Cc; dst[c * Kd + k] = src[id]; }
}
__global__ void pack_hdp(const float* __restrict__ src, float* __restrict__ dst) {
    int id = blockIdx.x * 256 + threadIdx.x;
    if (id < Hh * Dd * PHp) {
        int p = id % PHp, d = (id / PHp) % Dd, h = id / (PHp * Dd);
        dst[(h * PHp + p) * Dd + d] = src[id];
    }
}

// ---------------- row-dot: P[m,h] = dot(avec[h,:], X[m,:]) ----------------
__global__ __launch_bounds__(256) void rowdot(const float* __restrict__ X,
                                              const float* __restrict__ avec,
                                              float* __restrict__ P, int M)
{
    __shared__ float sa[Hh * Dd];
    int t = threadIdx.x;
    for (int i = t; i < Hh * Dd; i += 256) sa[i] = avec[i];
    __syncthreads();
    int row = blockIdx.x * 8 + (t >> 5);
    int lane = t & 31;
    const float* xr = X + (size_t)row * Dd;
    float acc[Hh] = {};
    #pragma unroll
    for (int j = 0; j < 8; j++) {
        float xv = xr[lane + 32 * j];
        #pragma unroll
        for (int h = 0; h < Hh; h++) acc[h] += sa[h * Dd + lane + 32 * j] * xv;
    }
    #pragma unroll
    for (int h = 0; h < Hh; h++) {
        #pragma unroll
        for (int o = 16; o > 0; o >>= 1) acc[h] += __shfl_down_sync(0xffffffffu, acc[h], o);
    }
    if (lane == 0) {
        #pragma unroll
        for (int h = 0; h < Hh; h++) P[(size_t)row * Hh + h] = acc[h];
    }
}

__device__ __forceinline__ float elu1(float x) { return x > 0.f ? x : expm1f(x); }

// ---------------- edge combine: eout = elu(EW + al0*Y[u] + al1*Y[v]) ----------------
__global__ __launch_bounds__(256) void edge_comb(const int* __restrict__ ena,
                                                 const float* __restrict__ pn,
                                                 const float* __restrict__ be,
                                                 const float* __restrict__ EW,
                                                 const float* __restrict__ Y,
                                                 float* __restrict__ eout)
{
    int gid = blockIdx.x * 256 + threadIdx.x;
    int e = gid >> 6, c4 = gid & 63, h = c4 >> 4;
    int u = ena[2 * e], v = ena[2 * e + 1];
    float b = be[(size_t)e * Hh + h];
    float s0 = pn[(size_t)u * Hh + h] + b;
    float s1 = pn[(size_t)v * Hh + h] + b;
    s0 = s0 > 0.f ? s0 : 0.2f * s0;
    s1 = s1 > 0.f ? s1 : 0.2f * s1;
    float m = fmaxf(s0, s1);
    float x0 = __expf(s0 - m), x1 = __expf(s1 - m);
    float inv = 1.f / (x0 + x1);
    float al0 = x0 * inv, al1 = x1 * inv;
    float4 ew = *(const float4*)(EW + (size_t)e * Dd + c4 * 4);
    float4 yu = *(const float4*)(Y + (size_t)u * Dd + c4 * 4);
    float4 yv = *(const float4*)(Y + (size_t)v * Dd + c4 * 4);
    float4 r;
    r.x = elu1(ew.x + al0 * yu.x + al1 * yv.x);
    r.y = elu1(ew.y + al0 * yu.y + al1 * yv.y);
    r.z = elu1(ew.z + al0 * yu.z + al1 * yv.z);
    r.w = elu1(ew.w + al0 * yu.w + al1 * yv.w);
    *(float4*)(eout + (size_t)e * Dd + c4 * 4) = r;
}

// ---------------- node aggregation: nag[h][n][:] = sum_k aln[h,k] * edges[idx_k] ----------------
__global__ __launch_bounds__(256) void nag_kernel(const int* __restrict__ n2e,
                                                  const float* __restrict__ ps,
                                                  const float* __restrict__ qe,
                                                  const float* __restrict__ edges,
                                                  float* __restrict__ nag)
{
    int t = threadIdx.x, w = t >> 5, lane = t & 31;
    int n = blockIdx.x * 8 + w;
    int idx[Kk];
    #pragma unroll
    for (int k = 0; k < Kk; k++) idx[k] = n2e[(size_t)n * Kk + k];
    float al[Hh][Kk];
    #pragma unroll
    for (int h = 0; h < Hh; h++) {
        float bs = ps[(size_t)n * Hh + h];
        float s[Kk]; float m = -1e30f;
        #pragma unroll
        for (int k = 0; k < Kk; k++) {
            float sv = bs + qe[(size_t)idx[k] * Hh + h];
            sv = sv > 0.f ? sv : 0.2f * sv;
            s[k] = sv; m = fmaxf(m, sv);
        }
        float sum = 0.f;
        #pragma unroll
        for (int k = 0; k < Kk; k++) { s[k] = __expf(s[k] - m); sum += s[k]; }
        float inv = 1.f / sum;
        #pragma unroll
        for (int k = 0; k < Kk; k++) al[h][k] = s[k] * inv;
    }
    float4 a0[Hh] = {}, a1[Hh] = {};
    #pragma unroll
    for (int k = 0; k < Kk; k++) {
        const float4* er = (const float4*)(edges + (size_t)idx[k] * Dd);
        float4 ea = er[lane], eb = er[32 + lane];
        #pragma unroll
        for (int h = 0; h < Hh; h++) {
            float a = al[h][k];
            a0[h].x += a * ea.x; a0[h].y += a * ea.y; a0[h].z += a * ea.z; a0[h].w += a * ea.w;
            a1[h].x += a * eb.x; a1[h].y += a * eb.y; a1[h].z += a * eb.z; a1[h].w += a * eb.w;
        }
    }
    #pragma unroll
    for (int h = 0; h < Hh; h++) {
        float* dst = nag + ((size_t)h * Nn + n) * Dd;
        *(float4*)(dst + lane * 4) = a0[h];
        *(float4*)(dst + 128 + lane * 4) = a1[h];
    }
}

// ---------------- node combine: nout = elu(S + NP) ----------------
__global__ __launch_bounds__(256) void node_comb(const float* __restrict__ S,
                                                 const float* __restrict__ NP,
                                                 float* __restrict__ out,
                                                 float* __restrict__ xout,
                                                 int Lofs, int writeX)
{
    int gid = blockIdx.x * 256 + threadIdx.x;
    int n = gid >> 6, c4 = gid & 63;
    float4 s = *(const float4*)(S + (size_t)n * Dd + c4 * 4);
    float4 p = *(const float4*)(NP + (size_t)n * Dd + c4 * 4);
    float4 r;
    r.x = elu1(s.x + p.x); r.y = elu1(s.y + p.y);
    r.z = elu1(s.z + p.z); r.w = elu1(s.w + p.w);
    *(float4*)(out + (size_t)n * (DEPTHc * Dd) + Lofs + c4 * 4) = r;
    if (writeX) *(float4*)(xout + (size_t)n * Dd + c4 * 4) = r;
}

// ---------------- launcher ----------------
extern "C" void kernel_launch(void* const* d_in, const int* in_sizes, int n_in,
                              void* d_out, int out_size)
{
    (void)in_sizes; (void)n_in; (void)out_size;
    const float* feats    = (const float*)d_in[0];
    const float* edge_emb = (const float*)d_in[1];
    const int*   ena      = (const int*)d_in[2];
    const int*   n2e      = (const int*)d_in[3];
    const float* Wp0      = (const float*)d_in[4];
    const float* Wp1      = (const float*)d_in[5];
    const float* Wep      = (const float*)d_in[6];
    const float* a_e      = (const float*)d_in[7];
    const float* a_n      = (const float*)d_in[8];
    const float* W_e      = (const float*)d_in[9];
    const float* a_s      = (const float*)d_in[10];
    const float* a_edge   = (const float*)d_in[11];
    const float* W_self   = (const float*)d_in[12];
    const float* W_nb     = (const float*)d_in[13];
    float* out = (float*)d_out;

    float *dummy, *base, *xb, *Y, *S, *NP, *eA, *eB, *EW, *nag, *pn, *be, *ps, *qe, *Bt0, *Bt1, *Bt2;
    cudaGetSymbolAddress((void**)&dummy, g_dummy);
    cudaGetSymbolAddress((void**)&base,  g_base);
    cudaGetSymbolAddress((void**)&xb,    g_x);
    cudaGetSymbolAddress((void**)&Y,     g_Y);
    cudaGetSymbolAddress((void**)&S,     g_S);
    cudaGetSymbolAddress((void**)&NP,    g_NP);
    cudaGetSymbolAddress((void**)&eA,    g_eA);
    cudaGetSymbolAddress((void**)&eB,    g_eB);
    cudaGetSymbolAddress((void**)&EW,    g_EW);
    cudaGetSymbolAddress((void**)&nag,   g_nag);
    cudaGetSymbolAddress((void**)&pn,    g_pn);
    cudaGetSymbolAddress((void**)&be,    g_be);
    cudaGetSymbolAddress((void**)&ps,    g_ps);
    cudaGetSymbolAddress((void**)&qe,    g_qe);
    cudaGetSymbolAddress((void**)&Bt0,   g_Bt0);
    cudaGetSymbolAddress((void**)&Bt1,   g_Bt1);
    cudaGetSymbolAddress((void**)&Bt2,   g_Bt2);

    dim3 blk(256);
    dim3 gN(Nn / 128, 2);    // N-rows GEMM, NCOLS=256
    dim3 gE(Ee / 128, 2);    // E-rows GEMM, NCOLS=256
    dim3 gH(Nn / 128, 1);    // per-head GEMM, NCOLS=64

    // preps
    pack2d<<<256, blk>>>(Wp0, Bt0, Dd, Dd);
    gemm_mma<128><<<gN, blk>>>(feats, Bt0, dummy, Dd, Dd);
    pack2d<<<256, blk>>>(Wp1, Bt1, Dd, Dd);
    gemm_mma<128><<<gN, blk>>>(feats, Bt1, base, Dd, Dd);

    for (int mp = 0; mp < NMPc; mp++) {
        const int* ena_mp = ena + (size_t)mp * Ee * 2;
        const int* n2e_mp = n2e + (size_t)mp * Nn * Kk;
        float* outmp = out + (size_t)mp * Nn * DEPTHc * Dd;

        // edges = edge_emb[mp] @ W_eprep[mp]
        pack2d<<<64, blk>>>(Wep + (size_t)mp * EDd * Dd, Bt2, EDd, Dd);
        gemm_mma<128><<<gE, blk>>>(edge_emb + (size_t)mp * Ee * EDd, Bt2, eA, EDd, Dd);

        // ---- layer 0: edge aggregator ----
        size_t pl0 = (size_t)(mp * DEPTHc + 0);
        rowdot<<<Nn / 8, blk>>>(base, a_n + pl0 * Hh * Dd, pn, Nn);
        rowdot<<<Ee / 8, blk>>>(eA,   a_e + pl0 * Hh * Dd, be, Ee);
        pack_hdp<<<256, blk>>>(W_e + pl0 * Hh * Dd * PHp, Bt0);
        gemm_mma<128><<<gE, blk>>>(eA,   Bt0, EW, Dd, Dd);
        gemm_mma<128><<<gN, blk>>>(base, Bt0, Y,  Dd, Dd);
        edge_comb<<<Ee * 64 / 256, blk>>>(ena_mp, pn, be, EW, Y, eB);

        // ---- layer 0: node aggregator (xin = dummy, edges = eA) ----
        rowdot<<<Nn / 8, blk>>>(dummy, a_s    + pl0 * Hh * Dd, ps, Nn);
        rowdot<<<Ee / 8, blk>>>(eA,    a_edge + pl0 * Hh * Dd, qe, Ee);
        nag_kernel<<<Nn / 8, blk>>>(n2e_mp, ps, qe, eA, nag);
        pack_hdp<<<256, blk>>>(W_self + pl0 * Hh * Dd * PHp, Bt1);
        gemm_mma<128><<<gN, blk>>>(dummy, Bt1, S, Dd, Dd);
        pack_hdp<<<256, blk>>>(W_nb + pl0 * Hh * Dd * PHp, Bt2);
        for (int h = 0; h < Hh; h++)
            gemm_mma<64><<<gH, blk>>>(nag + (size_t)h * Nn * Dd,
                                      Bt2 + (size_t)h * PHp * Dd,
                                      NP + h * PHp, Dd, Dd);
        node_comb<<<Nn * 64 / 256, blk>>>(S, NP, outmp, xb, 0, 1);

        // ---- layer 1: node aggregator only (xin = x, edges = eB) ----
        size_t pl1 = (size_t)(mp * DEPTHc + 1);
        rowdot<<<Nn / 8, blk>>>(xb, a_s    + pl1 * Hh * Dd, ps, Nn);
        rowdot<<<Ee / 8, blk>>>(eB, a_edge + pl1 * Hh * Dd, qe, Ee);
        nag_kernel<<<Nn / 8, blk>>>(n2e_mp, ps, qe, eB, nag);
        pack_hdp<<<256, blk>>>(W_self + pl1 * Hh * Dd * PHp, Bt1);
        gemm_mma<128><<<gN, blk>>>(xb, Bt1, S, Dd, Dd);
        pack_hdp<<<256, blk>>>(W_nb + pl1 * Hh * Dd * PHp, Bt2);
        for (int h = 0; h < Hh; h++)
            gemm_mma<64><<<gH, blk>>>(nag + (size_t)h * Nn * Dd,
                                      Bt2 + (size_t)h * PHp * Dd,
                                      NP + h * PHp, Dd, Dd);
        node_comb<<<Nn * 64 / 256, blk>>>(S, NP, outmp, xb, Dd, 0);
    }
}

// round 4
// speedup vs baseline: 3.2440x; 1.1267x over previous
#include <cuda_runtime.h>
#include <cuda_bf16.h>
#include <math.h>
#include <stdint.h>

#define Nn 65536
#define Ee 262144
#define Kk 8
#define NMPc 2
#define DEPTHc 2
#define Hh 4
#define Dd 256
#define PHp 64
#define EDd 64

// ---------------- scratch (device globals; no allocation allowed) ----------------
__device__ float g_db   [(size_t)2 * Nn * Dd];   // [0]=dummy, [1]=base
__device__ float g_x    [(size_t)Nn * Dd];
__device__ float g_Y    [(size_t)Nn * Dd];
__device__ float g_S    [(size_t)Nn * Dd];
__device__ float g_NP   [(size_t)Nn * Dd];
__device__ float g_eA   [(size_t)Ee * Dd];
__device__ float g_eB   [(size_t)Ee * Dd];
__device__ float g_EW   [(size_t)Ee * Dd];
__device__ float g_nag  [(size_t)Hh * Nn * Dd];
__device__ float g_pn   [(size_t)Nn * Hh];
__device__ float g_be   [(size_t)Ee * Hh];
__device__ float g_ps   [(size_t)Nn * Hh];
__device__ float g_qe   [(size_t)Ee * Hh];
__device__ float g_BtP  [2 * Dd * Dd];
__device__ float g_Bt0  [Dd * Dd];
__device__ float g_Bt1  [Dd * Dd];
__device__ float g_Bt2  [Dd * Dd];

// ---------------- HMMA helper ----------------
__device__ __forceinline__ void mma16816(float* c, const uint32_t* a, uint32_t b0, uint32_t b1) {
    asm volatile("mma.sync.aligned.m16n8k16.row.col.f32.bf16.bf16.f32 "
                 "{%0,%1,%2,%3}, {%4,%5,%6,%7}, {%8,%9}, {%0,%1,%2,%3};"
                 : "+f"(c[0]), "+f"(c[1]), "+f"(c[2]), "+f"(c[3])
                 : "r"(a[0]), "r"(a[1]), "r"(a[2]), "r"(a[3]), "r"(b0), "r"(b1));
}

__device__ __forceinline__ void split4(float4 v, uint2& hi, uint2& lo) {
    __nv_bfloat16 h0 = __float2bfloat16(v.x), h1 = __float2bfloat16(v.y);
    __nv_bfloat16 h2 = __float2bfloat16(v.z), h3 = __float2bfloat16(v.w);
    __nv_bfloat16 l0 = __float2bfloat16(v.x - __bfloat162float(h0));
    __nv_bfloat16 l1 = __float2bfloat16(v.y - __bfloat162float(h1));
    __nv_bfloat16 l2 = __float2bfloat16(v.z - __bfloat162float(h2));
    __nv_bfloat16 l3 = __float2bfloat16(v.w - __bfloat162float(h3));
    union { __nv_bfloat162 b[2]; uint2 u; } ph, pl;
    ph.b[0] = __nv_bfloat162(h0, h1); ph.b[1] = __nv_bfloat162(h2, h3);
    pl.b[0] = __nv_bfloat162(l0, l1); pl.b[1] = __nv_bfloat162(l2, l3);
    hi = ph.u; lo = pl.u;
}

// ---------------- pipelined bf16-split HMMA GEMM ----------------
// C[M, gridDim.y*BN] = A[M,K] @ Bt[*,K]^T ; z-batch via sAz/sBz/sCz element strides.
// Block tile 128(M) x BN(N), K-chunk 32, 8 warps = 4(M) x 2(N).
// Double-buffered smem + register prefetch: one __syncthreads per K-chunk.
template <int BN>
__global__ __launch_bounds__(256) void gemm_mma(const float* __restrict__ A,
                                                const float* __restrict__ Bt,
                                                float* __restrict__ C,
                                                int K, int ldc,
                                                size_t sAz, size_t sBz, size_t sCz)
{
    constexpr int NT  = BN / 16;
    constexpr int NB  = BN / 32;            // B float4 loads per thread
    constexpr int ASZ = 128 * 40;           // elems per A tile (hi or lo)
    constexpr int BSZ = BN * 40;
    constexpr int BUFE = 2 * ASZ + 2 * BSZ;
    extern __shared__ uint16_t sm[];

    A  += blockIdx.z * sAz;
    Bt += blockIdx.z * sBz;
    C  += blockIdx.z * sCz;

    int t = threadIdx.x, wid = t >> 5, lane = t & 31;
    int g = lane >> 2, tg = lane & 3;
    int wm = (wid >> 1) * 32;
    int wn = (wid & 1) * (BN / 2);
    size_t m0 = (size_t)blockIdx.x * 128;
    size_t n0 = (size_t)blockIdx.y * BN;
    const float* Abase = A + m0 * K;
    const float* Bbase = Bt + n0 * K;

    float acc[2][NT][4];
    #pragma unroll
    for (int mt = 0; mt < 2; mt++)
        #pragma unroll
        for (int nt = 0; nt < NT; nt++)
            #pragma unroll
            for (int j = 0; j < 4; j++) acc[mt][nt][j] = 0.f;

    float4 pa[4], pb[NB];
    auto ldAB = [&](int kb) {
        #pragma unroll
        for (int i = 0; i < 4; i++) {
            int id = t + 256 * i, r = id >> 3, c4 = id & 7;
            pa[i] = *(const float4*)(Abase + (size_t)r * K + kb * 32 + c4 * 4);
        }
        #pragma unroll
        for (int i = 0; i < NB; i++) {
            int id = t + 256 * i, r = id >> 3, c4 = id & 7;
            pb[i] = *(const float4*)(Bbase + (size_t)r * K + kb * 32 + c4 * 4);
        }
    };
    auto stAB = [&](int buf) {
        uint16_t* bAh = sm + buf * BUFE;
        uint16_t* bAl = bAh + ASZ;
        uint16_t* bBh = bAl + ASZ;
        uint16_t* bBl = bBh + BSZ;
        #pragma unroll
        for (int i = 0; i < 4; i++) {
            int id = t + 256 * i, r = id >> 3, c4 = id & 7;
            uint2 hi, lo; split4(pa[i], hi, lo);
            *(uint2*)&bAh[r * 40 + c4 * 4] = hi;
            *(uint2*)&bAl[r * 40 + c4 * 4] = lo;
        }
        #pragma unroll
        for (int i = 0; i < NB; i++) {
            int id = t + 256 * i, r = id >> 3, c4 = id & 7;
            uint2 hi, lo; split4(pb[i], hi, lo);
            *(uint2*)&bBh[r * 40 + c4 * 4] = hi;
            *(uint2*)&bBl[r * 40 + c4 * 4] = lo;
        }
    };
    auto domma = [&](int buf) {
        const uint16_t* bAh = sm + buf * BUFE;
        const uint16_t* bAl = bAh + ASZ;
        const uint16_t* bBh = bAl + ASZ;
        const uint16_t* bBl = bBh + BSZ;
        #pragma unroll
        for (int ks = 0; ks < 2; ks++) {
            int kc = ks * 16 + tg * 2;
            uint32_t ah[2][4], al_[2][4];
            #pragma unroll
            for (int mt = 0; mt < 2; mt++) {
                int row = wm + mt * 16 + g;
                ah[mt][0]  = *(const uint32_t*)&bAh[row * 40 + kc];
                ah[mt][1]  = *(const uint32_t*)&bAh[(row + 8) * 40 + kc];
                ah[mt][2]  = *(const uint32_t*)&bAh[row * 40 + kc + 8];
                ah[mt][3]  = *(const uint32_t*)&bAh[(row + 8) * 40 + kc + 8];
                al_[mt][0] = *(const uint32_t*)&bAl[row * 40 + kc];
                al_[mt][1] = *(const uint32_t*)&bAl[(row + 8) * 40 + kc];
                al_[mt][2] = *(const uint32_t*)&bAl[row * 40 + kc + 8];
                al_[mt][3] = *(const uint32_t*)&bAl[(row + 8) * 40 + kc + 8];
            }
            #pragma unroll
            for (int nt = 0; nt < NT; nt++) {
                int col = wn + nt * 8 + g;
                uint32_t bh0 = *(const uint32_t*)&bBh[col * 40 + kc];
                uint32_t bh1 = *(const uint32_t*)&bBh[col * 40 + kc + 8];
                uint32_t bl0 = *(const uint32_t*)&bBl[col * 40 + kc];
                uint32_t bl1 = *(const uint32_t*)&bBl[col * 40 + kc + 8];
                #pragma unroll
                for (int mt = 0; mt < 2; mt++) {
                    mma16816(acc[mt][nt], ah[mt],  bh0, bh1);
                    mma16816(acc[mt][nt], al_[mt], bh0, bh1);
                    mma16816(acc[mt][nt], ah[mt],  bl0, bl1);
                }
            }
        }
    };

    int nkb = K >> 5;
    ldAB(0);
    stAB(0);
    __syncthreads();
    for (int kb = 0; kb < nkb; kb++) {
        int cur = kb & 1;
        if (kb + 1 < nkb) ldAB(kb + 1);    // prefetch issues before MMAs
        domma(cur);
        if (kb + 1 < nkb) stAB(cur ^ 1);
        __syncthreads();
    }

    #pragma unroll
    for (int mt = 0; mt < 2; mt++) {
        size_t row = m0 + wm + mt * 16 + g;
        #pragma unroll
        for (int nt = 0; nt < NT; nt++) {
            size_t col = n0 + wn + nt * 8 + tg * 2;
            *(float2*)(C + row * ldc + col)       = make_float2(acc[mt][nt][0], acc[mt][nt][1]);
            *(float2*)(C + (row + 8) * ldc + col) = make_float2(acc[mt][nt][2], acc[mt][nt][3]);
        }
    }
}

// ---------------- weight packing ----------------
__global__ void pack2d(const float* __restrict__ src, float* __restrict__ dst, int Kd, int Cc) {
    int id = blockIdx.x * 256 + threadIdx.x;
    if (id < Kd * Cc) { int c = id % Cc, k = id / Cc; dst[c * Kd + k] = src[id]; }
}
__global__ void pack_hdp(const float* __restrict__ src, float* __restrict__ dst) {
    int id = blockIdx.x * 256 + threadIdx.x;
    if (id < Hh * Dd * PHp) {
        int p = id % PHp, d = (id / PHp) % Dd, h = id / (PHp * Dd);
        dst[(h * PHp + p) * Dd + d] = src[id];
    }
}

// ---------------- row-dot: P[m,h] = dot(avec[h,:], X[m,:]) ----------------
__global__ __launch_bounds__(256) void rowdot(const float* __restrict__ X,
                                              const float* __restrict__ avec,
                                              float* __restrict__ P, int M)
{
    __shared__ float sa[Hh * Dd];
    int t = threadIdx.x;
    for (int i = t; i < Hh * Dd; i += 256) sa[i] = avec[i];
    __syncthreads();
    int row = blockIdx.x * 8 + (t >> 5);
    int lane = t & 31;
    const float* xr = X + (size_t)row * Dd;
    float acc[Hh] = {};
    #pragma unroll
    for (int j = 0; j < 8; j++) {
        float xv = xr[lane + 32 * j];
        #pragma unroll
        for (int h = 0; h < Hh; h++) acc[h] += sa[h * Dd + lane + 32 * j] * xv;
    }
    #pragma unroll
    for (int h = 0; h < Hh; h++) {
        #pragma unroll
        for (int o = 16; o > 0; o >>= 1) acc[h] += __shfl_down_sync(0xffffffffu, acc[h], o);
    }
    if (lane == 0) {
        #pragma unroll
        for (int h = 0; h < Hh; h++) P[(size_t)row * Hh + h] = acc[h];
    }
}

// ---------------- dual row-dot: one pass over X, two projection sets ----------------
__global__ __launch_bounds__(256) void rowdot2(const float* __restrict__ X,
                                               const float* __restrict__ avec1,
                                               const float* __restrict__ avec2,
                                               float* __restrict__ P1,
                                               float* __restrict__ P2)
{
    __shared__ float sa[2 * Hh * Dd];
    int t = threadIdx.x;
    for (int i = t; i < Hh * Dd; i += 256) { sa[i] = avec1[i]; sa[Hh * Dd + i] = avec2[i]; }
    __syncthreads();
    int row = blockIdx.x * 8 + (t >> 5);
    int lane = t & 31;
    const float* xr = X + (size_t)row * Dd;
    float a1[Hh] = {}, a2[Hh] = {};
    #pragma unroll
    for (int j = 0; j < 8; j++) {
        float xv = xr[lane + 32 * j];
        #pragma unroll
        for (int h = 0; h < Hh; h++) {
            a1[h] += sa[h * Dd + lane + 32 * j] * xv;
            a2[h] += sa[Hh * Dd + h * Dd + lane + 32 * j] * xv;
        }
    }
    #pragma unroll
    for (int h = 0; h < Hh; h++) {
        #pragma unroll
        for (int o = 16; o > 0; o >>= 1) {
            a1[h] += __shfl_down_sync(0xffffffffu, a1[h], o);
            a2[h] += __shfl_down_sync(0xffffffffu, a2[h], o);
        }
    }
    if (lane == 0) {
        #pragma unroll
        for (int h = 0; h < Hh; h++) {
            P1[(size_t)row * Hh + h] = a1[h];
            P2[(size_t)row * Hh + h] = a2[h];
        }
    }
}

__device__ __forceinline__ float elu1(float x) { return x > 0.f ? x : expm1f(x); }

// ---------------- edge combine: eout = elu(EW + al0*Y[u] + al1*Y[v]) ----------------
__global__ __launch_bounds__(256) void edge_comb(const int* __restrict__ ena,
                                                 const float* __restrict__ pn,
                                                 const float* __restrict__ be,
                                                 const float* __restrict__ EW,
                                                 const float* __restrict__ Y,
                                                 float* __restrict__ eout)
{
    int gid = blockIdx.x * 256 + threadIdx.x;
    int e = gid >> 6, c4 = gid & 63, h = c4 >> 4;
    int u = ena[2 * e], v = ena[2 * e + 1];
    float b = be[(size_t)e * Hh + h];
    float s0 = pn[(size_t)u * Hh + h] + b;
    float s1 = pn[(size_t)v * Hh + h] + b;
    s0 = s0 > 0.f ? s0 : 0.2f * s0;
    s1 = s1 > 0.f ? s1 : 0.2f * s1;
    float m = fmaxf(s0, s1);
    float x0 = __expf(s0 - m), x1 = __expf(s1 - m);
    float inv = 1.f / (x0 + x1);
    float al0 = x0 * inv, al1 = x1 * inv;
    float4 ew = *(const float4*)(EW + (size_t)e * Dd + c4 * 4);
    float4 yu = *(const float4*)(Y + (size_t)u * Dd + c4 * 4);
    float4 yv = *(const float4*)(Y + (size_t)v * Dd + c4 * 4);
    float4 r;
    r.x = elu1(ew.x + al0 * yu.x + al1 * yv.x);
    r.y = elu1(ew.y + al0 * yu.y + al1 * yv.y);
    r.z = elu1(ew.z + al0 * yu.z + al1 * yv.z);
    r.w = elu1(ew.w + al0 * yu.w + al1 * yv.w);
    *(float4*)(eout + (size_t)e * Dd + c4 * 4) = r;
}

// ---------------- node aggregation ----------------
__global__ __launch_bounds__(256) void nag_kernel(const int* __restrict__ n2e,
                                                  const float* __restrict__ ps,
                                                  const float* __restrict__ qe,
                                                  const float* __restrict__ edges,
                                                  float* __restrict__ nag)
{
    int t = threadIdx.x, w = t >> 5, lane = t & 31;
    int n = blockIdx.x * 8 + w;
    int idx[Kk];
    #pragma unroll
    for (int k = 0; k < Kk; k++) idx[k] = n2e[(size_t)n * Kk + k];
    float al[Hh][Kk];
    #pragma unroll
    for (int h = 0; h < Hh; h++) {
        float bs = ps[(size_t)n * Hh + h];
        float s[Kk]; float m = -1e30f;
        #pragma unroll
        for (int k = 0; k < Kk; k++) {
            float sv = bs + qe[(size_t)idx[k] * Hh + h];
            sv = sv > 0.f ? sv : 0.2f * sv;
            s[k] = sv; m = fmaxf(m, sv);
        }
        float sum = 0.f;
        #pragma unroll
        for (int k = 0; k < Kk; k++) { s[k] = __expf(s[k] - m); sum += s[k]; }
        float inv = 1.f / sum;
        #pragma unroll
        for (int k = 0; k < Kk; k++) al[h][k] = s[k] * inv;
    }
    float4 a0[Hh] = {}, a1[Hh] = {};
    #pragma unroll
    for (int k = 0; k < Kk; k++) {
        const float4* er = (const float4*)(edges + (size_t)idx[k] * Dd);
        float4 ea = er[lane], eb = er[32 + lane];
        #pragma unroll
        for (int h = 0; h < Hh; h++) {
            float a = al[h][k];
            a0[h].x += a * ea.x; a0[h].y += a * ea.y; a0[h].z += a * ea.z; a0[h].w += a * ea.w;
            a1[h].x += a * eb.x; a1[h].y += a * eb.y; a1[h].z += a * eb.z; a1[h].w += a * eb.w;
        }
    }
    #pragma unroll
    for (int h = 0; h < Hh; h++) {
        float* dst = nag + ((size_t)h * Nn + n) * Dd;
        *(float4*)(dst + lane * 4) = a0[h];
        *(float4*)(dst + 128 + lane * 4) = a1[h];
    }
}

// ---------------- node combine: nout = elu(S + NP) ----------------
__global__ __launch_bounds__(256) void node_comb(const float* __restrict__ S,
                                                 const float* __restrict__ NP,
                                                 float* __restrict__ out,
                                                 float* __restrict__ xout,
                                                 int Lofs, int writeX)
{
    int gid = blockIdx.x * 256 + threadIdx.x;
    int n = gid >> 6, c4 = gid & 63;
    float4 s = *(const float4*)(S + (size_t)n * Dd + c4 * 4);
    float4 p = *(const float4*)(NP + (size_t)n * Dd + c4 * 4);
    float4 r;
    r.x = elu1(s.x + p.x); r.y = elu1(s.y + p.y);
    r.z = elu1(s.z + p.z); r.w = elu1(s.w + p.w);
    *(float4*)(out + (size_t)n * (DEPTHc * Dd) + Lofs + c4 * 4) = r;
    if (writeX) *(float4*)(xout + (size_t)n * Dd + c4 * 4) = r;
}

// ---------------- launcher ----------------
extern "C" void kernel_launch(void* const* d_in, const int* in_sizes, int n_in,
                              void* d_out, int out_size)
{
    (void)in_sizes; (void)n_in; (void)out_size;
    const float* feats    = (const float*)d_in[0];
    const float* edge_emb = (const float*)d_in[1];
    const int*   ena      = (const int*)d_in[2];
    const int*   n2e      = (const int*)d_in[3];
    const float* Wp0      = (const float*)d_in[4];
    const float* Wp1      = (const float*)d_in[5];
    const float* Wep      = (const float*)d_in[6];
    const float* a_e      = (const float*)d_in[7];
    const float* a_n      = (const float*)d_in[8];
    const float* W_e      = (const float*)d_in[9];
    const float* a_s      = (const float*)d_in[10];
    const float* a_edge   = (const float*)d_in[11];
    const float* W_self   = (const float*)d_in[12];
    const float* W_nb     = (const float*)d_in[13];
    float* out = (float*)d_out;

    float *db, *xb, *Y, *S, *NP, *eA, *eB, *EW, *nag, *pn, *be, *ps, *qe, *BtP, *Bt0, *Bt1, *Bt2;
    cudaGetSymbolAddress((void**)&db,  g_db);
    cudaGetSymbolAddress((void**)&xb,  g_x);
    cudaGetSymbolAddress((void**)&Y,   g_Y);
    cudaGetSymbolAddress((void**)&S,   g_S);
    cudaGetSymbolAddress((void**)&NP,  g_NP);
    cudaGetSymbolAddress((void**)&eA,  g_eA);
    cudaGetSymbolAddress((void**)&eB,  g_eB);
    cudaGetSymbolAddress((void**)&EW,  g_EW);
    cudaGetSymbolAddress((void**)&nag, g_nag);
    cudaGetSymbolAddress((void**)&pn,  g_pn);
    cudaGetSymbolAddress((void**)&be,  g_be);
    cudaGetSymbolAddress((void**)&ps,  g_ps);
    cudaGetSymbolAddress((void**)&qe,  g_qe);
    cudaGetSymbolAddress((void**)&BtP, g_BtP);
    cudaGetSymbolAddress((void**)&Bt0, g_Bt0);
    cudaGetSymbolAddress((void**)&Bt1, g_Bt1);
    cudaGetSymbolAddress((void**)&Bt2, g_Bt2);
    float* dummy = db;
    float* base  = db + (size_t)Nn * Dd;

    constexpr int SM128 = 2 * (2 * 128 * 40 + 2 * 128 * 40) * 2; // 81920 B
    constexpr int SM64  = 2 * (2 * 128 * 40 + 2 * 64 * 40) * 2;  // 61440 B
    cudaFuncSetAttribute(gemm_mma<128>, cudaFuncAttributeMaxDynamicSharedMemorySize, SM128);
    cudaFuncSetAttribute(gemm_mma<64>,  cudaFuncAttributeMaxDynamicSharedMemorySize, SM64);

    dim3 blk(256);
    dim3 gN(Nn / 128, 2);        // N-rows, 256 cols
    dim3 gE(Ee / 128, 2);        // E-rows, 256 cols
    dim3 gP(Nn / 128, 2, 2);     // preps z-batched
    dim3 gH(Nn / 128, 1, Hh);    // per-head GEMMs z-batched

    // preps: dummy = feats@Wp0 ; base = feats@Wp1 (one z=2 launch)
    pack2d<<<256, blk>>>(Wp0, BtP, Dd, Dd);
    pack2d<<<256, blk>>>(Wp1, BtP + Dd * Dd, Dd, Dd);
    gemm_mma<128><<<gP, blk, SM128>>>(feats, BtP, db, Dd, Dd,
                                      0, (size_t)Dd * Dd, (size_t)Nn * Dd);

    for (int mp = 0; mp < NMPc; mp++) {
        const int* ena_mp = ena + (size_t)mp * Ee * 2;
        const int* n2e_mp = n2e + (size_t)mp * Nn * Kk;
        float* outmp = out + (size_t)mp * Nn * DEPTHc * Dd;

        // edges = edge_emb[mp] @ W_eprep[mp]
        pack2d<<<64, blk>>>(Wep + (size_t)mp * EDd * Dd, Bt2, EDd, Dd);
        gemm_mma<128><<<gE, blk, SM128>>>(edge_emb + (size_t)mp * Ee * EDd, Bt2, eA,
                                          EDd, Dd, 0, 0, 0);

        // ---- layer 0: edge aggregator ----
        size_t pl0 = (size_t)(mp * DEPTHc + 0);
        rowdot<<<Nn / 8, blk>>>(base, a_n + pl0 * Hh * Dd, pn, Nn);
        // fused: be (a_e) and qe (a_edge) in one pass over eA
        rowdot2<<<Ee / 8, blk>>>(eA, a_e + pl0 * Hh * Dd, a_edge + pl0 * Hh * Dd, be, qe);
        pack_hdp<<<256, blk>>>(W_e + pl0 * Hh * Dd * PHp, Bt0);
        gemm_mma<128><<<gE, blk, SM128>>>(eA,   Bt0, EW, Dd, Dd, 0, 0, 0);
        gemm_mma<128><<<gN, blk, SM128>>>(base, Bt0, Y,  Dd, Dd, 0, 0, 0);
        edge_comb<<<Ee * 64 / 256, blk>>>(ena_mp, pn, be, EW, Y, eB);

        // ---- layer 0: node aggregator (xin = dummy, edges = eA) ----
        rowdot<<<Nn / 8, blk>>>(dummy, a_s + pl0 * Hh * Dd, ps, Nn);
        nag_kernel<<<Nn / 8, blk>>>(n2e_mp, ps, qe, eA, nag);
        pack_hdp<<<256, blk>>>(W_self + pl0 * Hh * Dd * PHp, Bt1);
        gemm_mma<128><<<gN, blk, SM128>>>(dummy, Bt1, S, Dd, Dd, 0, 0, 0);
        pack_hdp<<<256, blk>>>(W_nb + pl0 * Hh * Dd * PHp, Bt2);
        gemm_mma<64><<<gH, blk, SM64>>>(nag, Bt2, NP, Dd, Dd,
                                        (size_t)Nn * Dd, (size_t)PHp * Dd, (size_t)PHp);
        node_comb<<<Nn * 64 / 256, blk>>>(S, NP, outmp, xb, 0, 1);

        // ---- layer 1: node aggregator only (xin = x, edges = eB) ----
        size_t pl1 = (size_t)(mp * DEPTHc + 1);
        rowdot<<<Nn / 8, blk>>>(xb, a_s    + pl1 * Hh * Dd, ps, Nn);
        rowdot<<<Ee / 8, blk>>>(eB, a_edge + pl1 * Hh * Dd, qe, Ee);
        nag_kernel<<<Nn / 8, blk>>>(n2e_mp, ps, qe, eB, nag);
        pack_hdp<<<256, blk>>>(W_self + pl1 * Hh * Dd * PHp, Bt1);
        gemm_mma<128><<<gN, blk, SM128>>>(xb, Bt1, S, Dd, Dd, 0, 0, 0);
        pack_hdp<<<256, blk>>>(W_nb + pl1 * Hh * Dd * PHp, Bt2);
        gemm_mma<64><<<gH, blk, SM64>>>(nag, Bt2, NP, Dd, Dd,
                                        (size_t)Nn * Dd, (size_t)PHp * Dd, (size_t)PHp);
        node_comb<<<Nn * 64 / 256, blk>>>(S, NP, outmp, xb, Dd, 0);
    }
}

// round 6
// speedup vs baseline: 4.0321x; 1.2429x over previous
#include <cuda_runtime.h>
#include <cuda_bf16.h>
#include <math.h>
#include <stdint.h>

#define Nn 65536
#define Ee 262144
#define Kk 8
#define NMPc 2
#define DEPTHc 2
#define Hh 4
#define Dd 256
#define PHp 64
#define EDd 64

// ---------------- scratch (device globals; no allocation allowed) ----------------
__device__ __align__(16) float g_db  [(size_t)2 * Nn * Dd];   // [0]=dummy, [1]=base
__device__ __align__(16) float g_x   [(size_t)Nn * Dd];
__device__ __align__(16) float g_Y   [(size_t)Nn * Dd];
__device__ __align__(16) float g_S   [(size_t)Nn * Dd];
__device__ __align__(16) float g_NP  [(size_t)Nn * Dd];
__device__ __align__(16) float g_EW2 [(size_t)2 * Ee * Dd];   // [0]=EW, [1]=EWnb0
__device__ __align__(16) float g_eB  [(size_t)Ee * Dd];
__device__ __align__(16) float g_nag [(size_t)Hh * Nn * Dd];
__device__ __align__(16) float g_pn  [(size_t)Nn * Hh];
__device__ __align__(16) float g_be  [(size_t)Ee * Hh];       // be (L0), then qe1 (L1)
__device__ __align__(16) float g_ps  [(size_t)Nn * Hh];
__device__ __align__(16) float g_qe  [(size_t)Ee * Hh];       // qe0
__device__ __align__(16) float g_BtP [2 * Dd * Dd];
__device__ __align__(16) float g_Bt0 [Dd * Dd];
__device__ __align__(16) float g_Bt1 [Dd * Dd];
__device__ __align__(16) float g_Bt2 [Dd * Dd];
__device__ __align__(16) float g_Wc  [2 * Dd * EDd];          // folded weights (Bt layout, K=64)
__device__ __align__(16) float g_avf [2 * Hh * EDd];          // folded attention vecs

// ---------------- HMMA helper ----------------
__device__ __forceinline__ void mma16816(float* c, const uint32_t* a, uint32_t b0, uint32_t b1) {
    asm volatile("mma.sync.aligned.m16n8k16.row.col.f32.bf16.bf16.f32 "
                 "{%0,%1,%2,%3}, {%4,%5,%6,%7}, {%8,%9}, {%0,%1,%2,%3};"
                 : "+f"(c[0]), "+f"(c[1]), "+f"(c[2]), "+f"(c[3])
                 : "r"(a[0]), "r"(a[1]), "r"(a[2]), "r"(a[3]), "r"(b0), "r"(b1));
}

__device__ __forceinline__ void split4(float4 v, uint2& hi, uint2& lo) {
    __nv_bfloat16 h0 = __float2bfloat16(v.x), h1 = __float2bfloat16(v.y);
    __nv_bfloat16 h2 = __float2bfloat16(v.z), h3 = __float2bfloat16(v.w);
    __nv_bfloat16 l0 = __float2bfloat16(v.x - __bfloat162float(h0));
    __nv_bfloat16 l1 = __float2bfloat16(v.y - __bfloat162float(h1));
    __nv_bfloat16 l2 = __float2bfloat16(v.z - __bfloat162float(h2));
    __nv_bfloat16 l3 = __float2bfloat16(v.w - __bfloat162float(h3));
    union { __nv_bfloat162 b[2]; uint2 u; } ph, pl;
    ph.b[0] = __nv_bfloat162(h0, h1); ph.b[1] = __nv_bfloat162(h2, h3);
    pl.b[0] = __nv_bfloat162(l0, l1); pl.b[1] = __nv_bfloat162(l2, l3);
    hi = ph.u; lo = pl.u;
}

// ---------------- pipelined bf16-split HMMA GEMM ----------------
template <int BN>
__global__ __launch_bounds__(256) void gemm_mma(const float* __restrict__ A,
                                                const float* __restrict__ Bt,
                                                float* __restrict__ C,
                                                int K, int ldc,
                                                size_t sAz, size_t sBz, size_t sCz)
{
    constexpr int NT  = BN / 16;
    constexpr int NB  = BN / 32;
    constexpr int ASZ = 128 * 40;
    constexpr int BSZ = BN * 40;
    constexpr int BUFE = 2 * ASZ + 2 * BSZ;
    extern __shared__ uint16_t sm[];

    A  += blockIdx.z * sAz;
    Bt += blockIdx.z * sBz;
    C  += blockIdx.z * sCz;

    int t = threadIdx.x, wid = t >> 5, lane = t & 31;
    int g = lane >> 2, tg = lane & 3;
    int wm = (wid >> 1) * 32;
    int wn = (wid & 1) * (BN / 2);
    size_t m0 = (size_t)blockIdx.x * 128;
    size_t n0 = (size_t)blockIdx.y * BN;
    const float* Abase = A + m0 * K;
    const float* Bbase = Bt + n0 * K;

    float acc[2][NT][4];
    #pragma unroll
    for (int mt = 0; mt < 2; mt++)
        #pragma unroll
        for (int nt = 0; nt < NT; nt++)
            #pragma unroll
            for (int j = 0; j < 4; j++) acc[mt][nt][j] = 0.f;

    float4 pa[4], pb[NB];
    auto ldAB = [&](int kb) {
        #pragma unroll
        for (int i = 0; i < 4; i++) {
            int id = t + 256 * i, r = id >> 3, c4 = id & 7;
            pa[i] = *(const float4*)(Abase + (size_t)r * K + kb * 32 + c4 * 4);
        }
        #pragma unroll
        for (int i = 0; i < NB; i++) {
            int id = t + 256 * i, r = id >> 3, c4 = id & 7;
            pb[i] = *(const float4*)(Bbase + (size_t)r * K + kb * 32 + c4 * 4);
        }
    };
    auto stAB = [&](int buf) {
        uint16_t* bAh = sm + buf * BUFE;
        uint16_t* bAl = bAh + ASZ;
        uint16_t* bBh = bAl + ASZ;
        uint16_t* bBl = bBh + BSZ;
        #pragma unroll
        for (int i = 0; i < 4; i++) {
            int id = t + 256 * i, r = id >> 3, c4 = id & 7;
            uint2 hi, lo; split4(pa[i], hi, lo);
            *(uint2*)&bAh[r * 40 + c4 * 4] = hi;
            *(uint2*)&bAl[r * 40 + c4 * 4] = lo;
        }
        #pragma unroll
        for (int i = 0; i < NB; i++) {
            int id = t + 256 * i, r = id >> 3, c4 = id & 7;
            uint2 hi, lo; split4(pb[i], hi, lo);
            *(uint2*)&bBh[r * 40 + c4 * 4] = hi;
            *(uint2*)&bBl[r * 40 + c4 * 4] = lo;
        }
    };
    auto domma = [&](int buf) {
        const uint16_t* bAh = sm + buf * BUFE;
        const uint16_t* bAl = bAh + ASZ;
        const uint16_t* bBh = bAl + ASZ;
        const uint16_t* bBl = bBh + BSZ;
        #pragma unroll
        for (int ks = 0; ks < 2; ks++) {
            int kc = ks * 16 + tg * 2;
            uint32_t ah[2][4], al_[2][4];
            #pragma unroll
            for (int mt = 0; mt < 2; mt++) {
                int row = wm + mt * 16 + g;
                ah[mt][0]  = *(const uint32_t*)&bAh[row * 40 + kc];
                ah[mt][1]  = *(const uint32_t*)&bAh[(row + 8) * 40 + kc];
                ah[mt][2]  = *(const uint32_t*)&bAh[row * 40 + kc + 8];
                ah[mt][3]  = *(const uint32_t*)&bAh[(row + 8) * 40 + kc + 8];
                al_[mt][0] = *(const uint32_t*)&bAl[row * 40 + kc];
                al_[mt][1] = *(const uint32_t*)&bAl[(row + 8) * 40 + kc];
                al_[mt][2] = *(const uint32_t*)&bAl[row * 40 + kc + 8];
                al_[mt][3] = *(const uint32_t*)&bAl[(row + 8) * 40 + kc + 8];
            }
            #pragma unroll
            for (int nt = 0; nt < NT; nt++) {
                int col = wn + nt * 8 + g;
                uint32_t bh0 = *(const uint32_t*)&bBh[col * 40 + kc];
                uint32_t bh1 = *(const uint32_t*)&bBh[col * 40 + kc + 8];
                uint32_t bl0 = *(const uint32_t*)&bBl[col * 40 + kc];
                uint32_t bl1 = *(const uint32_t*)&bBl[col * 40 + kc + 8];
                #pragma unroll
                for (int mt = 0; mt < 2; mt++) {
                    mma16816(acc[mt][nt], ah[mt],  bh0, bh1);
                    mma16816(acc[mt][nt], al_[mt], bh0, bh1);
                    mma16816(acc[mt][nt], ah[mt],  bl0, bl1);
                }
            }
        }
    };

    int nkb = K >> 5;
    ldAB(0);
    stAB(0);
    __syncthreads();
    for (int kb = 0; kb < nkb; kb++) {
        int cur = kb & 1;
        if (kb + 1 < nkb) ldAB(kb + 1);
        domma(cur);
        if (kb + 1 < nkb) stAB(cur ^ 1);
        __syncthreads();
    }

    #pragma unroll
    for (int mt = 0; mt < 2; mt++) {
        size_t row = m0 + wm + mt * 16 + g;
        #pragma unroll
        for (int nt = 0; nt < NT; nt++) {
            size_t col = n0 + wn + nt * 8 + tg * 2;
            *(float2*)(C + row * ldc + col)       = make_float2(acc[mt][nt][0], acc[mt][nt][1]);
            *(float2*)(C + (row + 8) * ldc + col) = make_float2(acc[mt][nt][2], acc[mt][nt][3]);
        }
    }
}

// ---------------- weight packing ----------------
__global__ void pack2d(const float* __restrict__ src, float* __restrict__ dst, int Kd, int Cc) {
    int id = blockIdx.x * 256 + threadIdx.x;
    if (id < Kd * Cc) { int c = id % Cc, k = id / Cc; dst[c * Kd + k] = src[id]; }
}
__global__ void pack_hdp(const float* __restrict__ src, float* __restrict__ dst) {
    int id = blockIdx.x * 256 + threadIdx.x;
    if (id < Hh * Dd * PHp) {
        int p = id % PHp, d = (id / PHp) % Dd, h = id / (PHp * Dd);
        dst[(h * PHp + p) * Dd + d] = src[id];
    }
}

// ---------------- weight folding: Wc[c,j] = sum_d Wep[j,d] * BtW[c,d] ----------------
__global__ __launch_bounds__(256) void foldW(const float* __restrict__ Wep,
                                             const float* __restrict__ BtW,
                                             float* __restrict__ Wc)
{
    __shared__ float sB[4][256];
    int t = threadIdx.x;
    int c0 = blockIdx.x * 4;
    for (int i = t; i < 4 * 256; i += 256)
        sB[i >> 8][i & 255] = BtW[(size_t)(c0 + (i >> 8)) * 256 + (i & 255)];
    __syncthreads();
    int cl = t >> 6, j = t & 63;
    const float* wr = Wep + (size_t)j * 256;
    float acc = 0.f;
    #pragma unroll 8
    for (int d = 0; d < 256; d++) acc += wr[d] * sB[cl][d];
    Wc[(size_t)(c0 + cl) * 64 + j] = acc;
}

// ---------------- attention vec folding: out[s][h][j] = sum_d Wep[j,d]*a_s[h,d] ----------------
__global__ __launch_bounds__(256) void foldA2(const float* __restrict__ Wep,
                                              const float* __restrict__ a1,
                                              const float* __restrict__ a2,
                                              float* __restrict__ outp)
{
    __shared__ float s1[Hh * 256], s2[Hh * 256];
    int t = threadIdx.x;
    for (int i = t; i < Hh * 256; i += 256) { s1[i] = a1[i]; s2[i] = a2[i]; }
    __syncthreads();
    int h = t >> 6, j = t & 63;
    const float* wr = Wep + (size_t)j * 256;
    float A = 0.f, B = 0.f;
    #pragma unroll 8
    for (int d = 0; d < 256; d++) { float w = wr[d]; A += w * s1[h * 256 + d]; B += w * s2[h * 256 + d]; }
    outp[h * 64 + j] = A;
    outp[Hh * 64 + h * 64 + j] = B;
}

// ---------------- row-dot (D=256): P[m,h] = dot(avec[h,:], X[m,:]) ----------------
__global__ __launch_bounds__(256) void rowdot(const float* __restrict__ X,
                                              const float* __restrict__ avec,
                                              float* __restrict__ P, int M)
{
    __shared__ float sa[Hh * Dd];
    int t = threadIdx.x;
    for (int i = t; i < Hh * Dd; i += 256) sa[i] = avec[i];
    __syncthreads();
    int row = blockIdx.x * 8 + (t >> 5);
    int lane = t & 31;
    const float* xr = X + (size_t)row * Dd;
    float acc[Hh] = {};
    #pragma unroll
    for (int j = 0; j < 8; j++) {
        float xv = xr[lane + 32 * j];
        #pragma unroll
        for (int h = 0; h < Hh; h++) acc[h] += sa[h * Dd + lane + 32 * j] * xv;
    }
    #pragma unroll
    for (int h = 0; h < Hh; h++) {
        #pragma unroll
        for (int o = 16; o > 0; o >>= 1) acc[h] += __shfl_down_sync(0xffffffffu, acc[h], o);
    }
    if (lane == 0) {
        #pragma unroll
        for (int h = 0; h < Hh; h++) P[(size_t)row * Hh + h] = acc[h];
    }
}

// ---------------- dual row-dot over D=64 rows (edge_emb) ----------------
__global__ __launch_bounds__(256) void rowdot2_64(const float* __restrict__ X,
                                                  const float* __restrict__ avf,
                                                  float* __restrict__ P1,
                                                  float* __restrict__ P2)
{
    __shared__ float sa[2 * Hh * 64];
    int t = threadIdx.x;
    for (int i = t; i < 2 * Hh * 64; i += 256) sa[i] = avf[i];
    __syncthreads();
    int row = blockIdx.x * 8 + (t >> 5);
    int lane = t & 31;
    const float* xr = X + (size_t)row * 64;
    float x0 = xr[lane], x1 = xr[lane + 32];
    float a1[Hh], a2[Hh];
    #pragma unroll
    for (int h = 0; h < Hh; h++) {
        a1[h] = sa[h * 64 + lane] * x0 + sa[h * 64 + lane + 32] * x1;
        a2[h] = sa[256 + h * 64 + lane] * x0 + sa[256 + h * 64 + lane + 32] * x1;
    }
    #pragma unroll
    for (int h = 0; h < Hh; h++) {
        #pragma unroll
        for (int o = 16; o > 0; o >>= 1) {
            a1[h] += __shfl_down_sync(0xffffffffu, a1[h], o);
            a2[h] += __shfl_down_sync(0xffffffffu, a2[h], o);
        }
    }
    if (lane == 0) {
        #pragma unroll
        for (int h = 0; h < Hh; h++) {
            P1[(size_t)row * Hh + h] = a1[h];
            P2[(size_t)row * Hh + h] = a2[h];
        }
    }
}

__device__ __forceinline__ float elu1(float x) { return x > 0.f ? x : expm1f(x); }

// ---------------- edge combine + fused qe1 ----------------
__global__ __launch_bounds__(256) void edge_comb_q(const int* __restrict__ ena,
                                                   const float* __restrict__ pn,
                                                   const float* __restrict__ be,
                                                   const float* __restrict__ EW,
                                                   const float* __restrict__ Y,
                                                   const float* __restrict__ a1v,
                                                   float* __restrict__ eout,
                                                   float* __restrict__ qe1)
{
    __shared__ float sa1[Hh * Dd];
    __shared__ float sred[4][2][Hh];
    int t = threadIdx.x;
    for (int i = t; i < Hh * Dd; i += 256) sa1[i] = a1v[i];
    __syncthreads();

    int e0 = blockIdx.x * 4;
    int el = t >> 6, c4 = t & 63, h = c4 >> 4;
    int e = e0 + el;
    int u = ena[2 * e], v = ena[2 * e + 1];
    float b = be[(size_t)e * Hh + h];
    float s0 = pn[(size_t)u * Hh + h] + b;
    float s1 = pn[(size_t)v * Hh + h] + b;
    s0 = s0 > 0.f ? s0 : 0.2f * s0;
    s1 = s1 > 0.f ? s1 : 0.2f * s1;
    float m = fmaxf(s0, s1);
    float x0 = __expf(s0 - m), x1 = __expf(s1 - m);
    float inv = 1.f / (x0 + x1);
    float al0 = x0 * inv, al1 = x1 * inv;
    float4 ew = *(const float4*)(EW + (size_t)e * Dd + c4 * 4);
    float4 yu = *(const float4*)(Y + (size_t)u * Dd + c4 * 4);
    float4 yv = *(const float4*)(Y + (size_t)v * Dd + c4 * 4);
    float4 r;
    r.x = elu1(ew.x + al0 * yu.x + al1 * yv.x);
    r.y = elu1(ew.y + al0 * yu.y + al1 * yv.y);
    r.z = elu1(ew.z + al0 * yu.z + al1 * yv.z);
    r.w = elu1(ew.w + al0 * yu.w + al1 * yv.w);
    *(float4*)(eout + (size_t)e * Dd + c4 * 4) = r;

    float p[Hh];
    #pragma unroll
    for (int hh = 0; hh < Hh; hh++) {
        const float* av = sa1 + hh * Dd + c4 * 4;
        p[hh] = r.x * av[0] + r.y * av[1] + r.z * av[2] + r.w * av[3];
    }
    #pragma unroll
    for (int hh = 0; hh < Hh; hh++) {
        #pragma unroll
        for (int o = 16; o > 0; o >>= 1) p[hh] += __shfl_down_sync(0xffffffffu, p[hh], o);
    }
    int wl = t & 31, whalf = (t >> 5) & 1;
    if (wl == 0) {
        #pragma unroll
        for (int hh = 0; hh < Hh; hh++) sred[el][whalf][hh] = p[hh];
    }
    __syncthreads();
    if (t < 16) {
        int ee = t >> 2, hh = t & 3;
        qe1[(size_t)(e0 + ee) * Hh + hh] = sred[ee][0][hh] + sred[ee][1][hh];
    }
}

// ---------------- L0 node agg, projected ----------------
__global__ __launch_bounds__(256) void nagp_kernel(const int* __restrict__ n2e,
                                                   const float* __restrict__ ps,
                                                   const float* __restrict__ qe,
                                                   const float* __restrict__ EWnb,
                                                   float* __restrict__ NP)
{
    int t = threadIdx.x, w = t >> 5, lane = t & 31;
    int n = blockIdx.x * 8 + w;
    int idx[Kk];
    #pragma unroll
    for (int k = 0; k < Kk; k++) idx[k] = n2e[(size_t)n * Kk + k];
    float al[Hh][Kk];
    #pragma unroll
    for (int h = 0; h < Hh; h++) {
        float bs = ps[(size_t)n * Hh + h];
        float s[Kk]; float m = -1e30f;
        #pragma unroll
        for (int k = 0; k < Kk; k++) {
            float sv = bs + qe[(size_t)idx[k] * Hh + h];
            sv = sv > 0.f ? sv : 0.2f * sv;
            s[k] = sv; m = fmaxf(m, sv);
        }
        float sum = 0.f;
        #pragma unroll
        for (int k = 0; k < Kk; k++) { s[k] = __expf(s[k] - m); sum += s[k]; }
        float inv = 1.f / sum;
        #pragma unroll
        for (int k = 0; k < Kk; k++) al[h][k] = s[k] * inv;
    }
    int h0 = lane >> 4, h1 = 2 + (lane >> 4);
    float4 a0 = make_float4(0.f, 0.f, 0.f, 0.f), a1 = a0;
    #pragma unroll
    for (int k = 0; k < Kk; k++) {
        const float4* er = (const float4*)(EWnb + (size_t)idx[k] * Dd);
        float4 ea = er[lane], eb = er[32 + lane];
        float w0 = al[h0][k], w1 = al[h1][k];
        a0.x += w0 * ea.x; a0.y += w0 * ea.y; a0.z += w0 * ea.z; a0.w += w0 * ea.w;
        a1.x += w1 * eb.x; a1.y += w1 * eb.y; a1.z += w1 * eb.z; a1.w += w1 * eb.w;
    }
    *(float4*)(NP + (size_t)n * Dd + lane * 4)       = a0;
    *(float4*)(NP + (size_t)n * Dd + 128 + lane * 4) = a1;
}

// ---------------- L1 node aggregation (full) ----------------
__global__ __launch_bounds__(256) void nag_kernel(const int* __restrict__ n2e,
                                                  const float* __restrict__ ps,
                                                  const float* __restrict__ qe,
                                                  const float* __restrict__ edges,
                                                  float* __restrict__ nag)
{
    int t = threadIdx.x, w = t >> 5, lane = t & 31;
    int n = blockIdx.x * 8 + w;
    int idx[Kk];
    #pragma unroll
    for (int k = 0; k < Kk; k++) idx[k] = n2e[(size_t)n * Kk + k];
    float al[Hh][Kk];
    #pragma unroll
    for (int h = 0; h < Hh; h++) {
        float bs = ps[(size_t)n * Hh + h];
        float s[Kk]; float m = -1e30f;
        #pragma unroll
        for (int k = 0; k < Kk; k++) {
            float sv = bs + qe[(size_t)idx[k] * Hh + h];
            sv = sv > 0.f ? sv : 0.2f * sv;
            s[k] = sv; m = fmaxf(m, sv);
        }
        float sum = 0.f;
        #pragma unroll
        for (int k = 0; k < Kk; k++) { s[k] = __expf(s[k] - m); sum += s[k]; }
        float inv = 1.f / sum;
        #pragma unroll
        for (int k = 0; k < Kk; k++) al[h][k] = s[k] * inv;
    }
    float4 a0[Hh] = {}, a1[Hh] = {};
    #pragma unroll
    for (int k = 0; k < Kk; k++) {
        const float4* er = (const float4*)(edges + (size_t)idx[k] * Dd);
        float4 ea = er[lane], eb = er[32 + lane];
        #pragma unroll
        for (int h = 0; h < Hh; h++) {
            float a = al[h][k];
            a0[h].x += a * ea.x; a0[h].y += a * ea.y; a0[h].z += a * ea.z; a0[h].w += a * ea.w;
            a1[h].x += a * eb.x; a1[h].y += a * eb.y; a1[h].z += a * eb.z; a1[h].w += a * eb.w;
        }
    }
    #pragma unroll
    for (int h = 0; h < Hh; h++) {
        float* dst = nag + ((size_t)h * Nn + n) * Dd;
        *(float4*)(dst + lane * 4) = a0[h];
        *(float4*)(dst + 128 + lane * 4) = a1[h];
    }
}

// ---------------- node combine ----------------
__global__ __launch_bounds__(256) void node_comb(const float* __restrict__ S,
                                                 const float* __restrict__ NP,
                                                 float* __restrict__ out,
                                                 float* __restrict__ xout,
                                                 int Lofs, int writeX)
{
    int gid = blockIdx.x * 256 + threadIdx.x;
    int n = gid >> 6, c4 = gid & 63;
    float4 s = *(const float4*)(S + (size_t)n * Dd + c4 * 4);
    float4 p = *(const float4*)(NP + (size_t)n * Dd + c4 * 4);
    float4 r;
    r.x = elu1(s.x + p.x); r.y = elu1(s.y + p.y);
    r.z = elu1(s.z + p.z); r.w = elu1(s.w + p.w);
    *(float4*)(out + (size_t)n * (DEPTHc * Dd) + Lofs + c4 * 4) = r;
    if (writeX) *(float4*)(xout + (size_t)n * Dd + c4 * 4) = r;
}

// ---------------- launcher ----------------
extern "C" void kernel_launch(void* const* d_in, const int* in_sizes, int n_in,
                              void* d_out, int out_size)
{
    (void)in_sizes; (void)n_in; (void)out_size;
    const float* feats    = (const float*)d_in[0];
    const float* edge_emb = (const float*)d_in[1];
    const int*   ena      = (const int*)d_in[2];
    const int*   n2e      = (const int*)d_in[3];
    const float* Wp0      = (const float*)d_in[4];
    const float* Wp1      = (const float*)d_in[5];
    const float* Wep      = (const float*)d_in[6];
    const float* a_e      = (const float*)d_in[7];
    const float* a_n      = (const float*)d_in[8];
    const float* W_e      = (const float*)d_in[9];
    const float* a_s      = (const float*)d_in[10];
    const float* a_edge   = (const float*)d_in[11];
    const float* W_self   = (const float*)d_in[12];
    const float* W_nb     = (const float*)d_in[13];
    float* out = (float*)d_out;

    float *db, *xb, *Y, *S, *NP, *EW2, *eB, *nag, *pn, *be, *ps, *qe, *BtP, *Bt0, *Bt1, *Bt2, *Wc, *avf;
    cudaGetSymbolAddress((void**)&db,  g_db);
    cudaGetSymbolAddress((void**)&xb,  g_x);
    cudaGetSymbolAddress((void**)&Y,   g_Y);
    cudaGetSymbolAddress((void**)&S,   g_S);
    cudaGetSymbolAddress((void**)&NP,  g_NP);
    cudaGetSymbolAddress((void**)&EW2, g_EW2);
    cudaGetSymbolAddress((void**)&eB,  g_eB);
    cudaGetSymbolAddress((void**)&nag, g_nag);
    cudaGetSymbolAddress((void**)&pn,  g_pn);
    cudaGetSymbolAddress((void**)&be,  g_be);
    cudaGetSymbolAddress((void**)&ps,  g_ps);
    cudaGetSymbolAddress((void**)&qe,  g_qe);
    cudaGetSymbolAddress((void**)&BtP, g_BtP);
    cudaGetSymbolAddress((void**)&Bt0, g_Bt0);
    cudaGetSymbolAddress((void**)&Bt1, g_Bt1);
    cudaGetSymbolAddress((void**)&Bt2, g_Bt2);
    cudaGetSymbolAddress((void**)&Wc,  g_Wc);
    cudaGetSymbolAddress((void**)&avf, g_avf);
    float* dummy = db;
    float* base  = db + (size_t)Nn * Dd;
    float* EW    = EW2;
    float* EWnb0 = EW2 + (size_t)Ee * Dd;

    constexpr int SM128 = 2 * (2 * 128 * 40 + 2 * 128 * 40) * 2; // 81920 B
    constexpr int SM64  = 2 * (2 * 128 * 40 + 2 * 64 * 40) * 2;  // 61440 B
    cudaFuncSetAttribute(gemm_mma<128>, cudaFuncAttributeMaxDynamicSharedMemorySize, SM128);
    cudaFuncSetAttribute(gemm_mma<64>,  cudaFuncAttributeMaxDynamicSharedMemorySize, SM64);

    dim3 blk(256);
    dim3 gN(Nn / 128, 2);         // N-rows, 256 cols
    dim3 gE2(Ee / 128, 2, 2);     // E-rows, 256 cols, z=2 (EW + EWnb0)
    dim3 gP(Nn / 128, 2, 2);      // preps z-batched
    dim3 gH(Nn / 128, 1, Hh);     // per-head GEMMs z-batched

    // preps: dummy = feats@Wp0 ; base = feats@Wp1
    pack2d<<<256, blk>>>(Wp0, BtP, Dd, Dd);
    pack2d<<<256, blk>>>(Wp1, BtP + Dd * Dd, Dd, Dd);
    gemm_mma<128><<<gP, blk, SM128>>>(feats, BtP, db, Dd, Dd,
                                      0, (size_t)Dd * Dd, (size_t)Nn * Dd);

    for (int mp = 0; mp < NMPc; mp++) {
        const int*   ena_mp = ena + (size_t)mp * Ee * 2;
        const int*   n2e_mp = n2e + (size_t)mp * Nn * Kk;
        const float* emb_mp = edge_emb + (size_t)mp * Ee * EDd;
        const float* Wep_mp = Wep + (size_t)mp * EDd * Dd;
        float* outmp = out + (size_t)mp * Nn * DEPTHc * Dd;
        size_t pl0 = (size_t)(mp * DEPTHc + 0);
        size_t pl1 = (size_t)(mp * DEPTHc + 1);

        // fold weights: Wc[0] = Wep@W_e(L0), Wc[1] = Wep@W_nb(L0); fold attention vecs
        pack_hdp<<<256, blk>>>(W_e  + pl0 * Hh * Dd * PHp, Bt0);
        pack_hdp<<<256, blk>>>(W_nb + pl0 * Hh * Dd * PHp, Bt2);
        foldW<<<64, blk>>>(Wep_mp, Bt0, Wc);
        foldW<<<64, blk>>>(Wep_mp, Bt2, Wc + Dd * EDd);
        foldA2<<<1, blk>>>(Wep_mp, a_e + pl0 * Hh * Dd, a_edge + pl0 * Hh * Dd, avf);

        // EW = edge_emb@Wc0 ; EWnb0 = edge_emb@Wc1  (z=2, K=64)
        gemm_mma<128><<<gE2, blk, SM128>>>(emb_mp, Wc, EW2, EDd, Dd,
                                           0, (size_t)Dd * EDd, (size_t)Ee * Dd);

        // attention logits
        rowdot<<<Nn / 8, blk>>>(base, a_n + pl0 * Hh * Dd, pn, Nn);
        rowdot2_64<<<Ee / 8, blk>>>(emb_mp, avf, be, qe);      // be, qe0

        // Y = base @ W_e(L0)
        gemm_mma<128><<<gN, blk, SM128>>>(base, Bt0, Y, Dd, Dd, 0, 0, 0);

        // eB = elu(EW + attn(Y)) with fused qe1 (written into g_be, safe per-block)
        edge_comb_q<<<Ee / 4, blk>>>(ena_mp, pn, be, EW, Y,
                                     a_edge + pl1 * Hh * Dd, eB, be);

        // ---- layer 0 node aggregator (projected path) ----
        rowdot<<<Nn / 8, blk>>>(dummy, a_s + pl0 * Hh * Dd, ps, Nn);
        nagp_kernel<<<Nn / 8, blk>>>(n2e_mp, ps, qe, EWnb0, NP);
        pack_hdp<<<256, blk>>>(W_self + pl0 * Hh * Dd * PHp, Bt1);
        gemm_mma<128><<<gN, blk, SM128>>>(dummy, Bt1, S, Dd, Dd, 0, 0, 0);
        node_comb<<<Nn * 64 / 256, blk>>>(S, NP, outmp, xb, 0, 1);

        // ---- layer 1 node aggregator ----
        rowdot<<<Nn / 8, blk>>>(xb, a_s + pl1 * Hh * Dd, ps, Nn);
        nag_kernel<<<Nn / 8, blk>>>(n2e_mp, ps, be, eB, nag);   // be holds qe1 now
        pack_hdp<<<256, blk>>>(W_nb + pl1 * Hh * Dd * PHp, Bt2);
        gemm_mma<64><<<gH, blk, SM64>>>(nag, Bt2, NP, Dd, Dd,
                                        (size_t)Nn * Dd, (size_t)PHp * Dd, (size_t)PHp);
        pack_hdp<<<256, blk>>>(W_self + pl1 * Hh * Dd * PHp, Bt1);
        gemm_mma<128><<<gN, blk, SM128>>>(xb, Bt1, S, Dd, Dd, 0, 0, 0);
        node_comb<<<Nn * 64 / 256, blk>>>(S, NP, outmp, xb, Dd, 0);
    }
}

// round 7
// speedup vs baseline: 4.1691x; 1.0340x over previous
#include <cuda_runtime.h>
#include <cuda_bf16.h>
#include <math.h>
#include <stdint.h>

#define Nn 65536
#define Ee 262144
#define Kk 8
#define NMPc 2
#define DEPTHc 2
#define Hh 4
#define Dd 256
#define PHp 64
#define EDd 64

// ---------------- scratch (device globals; no allocation allowed) ----------------
__device__ __align__(16) float g_x    [(size_t)Nn * Dd];
__device__ __align__(16) float g_YS   [(size_t)2 * Nn * Dd];   // [0]=Y, [1]=S
__device__ __align__(16) float g_NP   [(size_t)Nn * Dd];
__device__ __align__(16) float g_EW2  [(size_t)2 * Ee * Dd];   // [0]=EW, [1]=EWnb0
__device__ __align__(16) float g_eB   [(size_t)Ee * Dd];
__device__ __align__(16) float g_nag  [(size_t)Hh * Nn * Dd];
__device__ __align__(16) float g_pn   [(size_t)Nn * Hh];
__device__ __align__(16) float g_be   [(size_t)Ee * Hh];       // be (L0), then qe1 (L1)
__device__ __align__(16) float g_ps   [(size_t)Nn * Hh];
__device__ __align__(16) float g_qe   [(size_t)Ee * Hh];       // qe0
__device__ __align__(16) float g_WpT  [2 * Dd * Dd];           // [0]=Wp0^T, [1]=Wp1^T
__device__ __align__(16) float g_Bt0  [Dd * Dd];
__device__ __align__(16) float g_Bt1  [Dd * Dd];
__device__ __align__(16) float g_Bt2  [Dd * Dd];
__device__ __align__(16) float g_WfYS [2 * Dd * Dd];           // folded [0]=WfY, [1]=WfS
__device__ __align__(16) float g_Wc   [2 * Dd * EDd];          // folded edge weights (K=64)
__device__ __align__(16) float g_avf  [2 * Hh * EDd];          // folded edge attention vecs
__device__ __align__(16) float g_av256[2 * Hh * Dd];           // folded node attention vecs

// ---------------- HMMA helper ----------------
__device__ __forceinline__ void mma16816(float* c, const uint32_t* a, uint32_t b0, uint32_t b1) {
    asm volatile("mma.sync.aligned.m16n8k16.row.col.f32.bf16.bf16.f32 "
                 "{%0,%1,%2,%3}, {%4,%5,%6,%7}, {%8,%9}, {%0,%1,%2,%3};"
                 : "+f"(c[0]), "+f"(c[1]), "+f"(c[2]), "+f"(c[3])
                 : "r"(a[0]), "r"(a[1]), "r"(a[2]), "r"(a[3]), "r"(b0), "r"(b1));
}

__device__ __forceinline__ void split4(float4 v, uint2& hi, uint2& lo) {
    __nv_bfloat16 h0 = __float2bfloat16(v.x), h1 = __float2bfloat16(v.y);
    __nv_bfloat16 h2 = __float2bfloat16(v.z), h3 = __float2bfloat16(v.w);
    __nv_bfloat16 l0 = __float2bfloat16(v.x - __bfloat162float(h0));
    __nv_bfloat16 l1 = __float2bfloat16(v.y - __bfloat162float(h1));
    __nv_bfloat16 l2 = __float2bfloat16(v.z - __bfloat162float(h2));
    __nv_bfloat16 l3 = __float2bfloat16(v.w - __bfloat162float(h3));
    union { __nv_bfloat162 b[2]; uint2 u; } ph, pl;
    ph.b[0] = __nv_bfloat162(h0, h1); ph.b[1] = __nv_bfloat162(h2, h3);
    pl.b[0] = __nv_bfloat162(l0, l1); pl.b[1] = __nv_bfloat162(l2, l3);
    hi = ph.u; lo = pl.u;
}

// ---------------- pipelined bf16-split HMMA GEMM ----------------
template <int BN>
__global__ __launch_bounds__(256) void gemm_mma(const float* __restrict__ A,
                                                const float* __restrict__ Bt,
                                                float* __restrict__ C,
                                                int K, int ldc,
                                                size_t sAz, size_t sBz, size_t sCz)
{
    constexpr int NT  = BN / 16;
    constexpr int NB  = BN / 32;
    constexpr int ASZ = 128 * 40;
    constexpr int BSZ = BN * 40;
    constexpr int BUFE = 2 * ASZ + 2 * BSZ;
    extern __shared__ uint16_t sm[];

    A  += blockIdx.z * sAz;
    Bt += blockIdx.z * sBz;
    C  += blockIdx.z * sCz;

    int t = threadIdx.x, wid = t >> 5, lane = t & 31;
    int g = lane >> 2, tg = lane & 3;
    int wm = (wid >> 1) * 32;
    int wn = (wid & 1) * (BN / 2);
    size_t m0 = (size_t)blockIdx.x * 128;
    size_t n0 = (size_t)blockIdx.y * BN;
    const float* Abase = A + m0 * K;
    const float* Bbase = Bt + n0 * K;

    float acc[2][NT][4];
    #pragma unroll
    for (int mt = 0; mt < 2; mt++)
        #pragma unroll
        for (int nt = 0; nt < NT; nt++)
            #pragma unroll
            for (int j = 0; j < 4; j++) acc[mt][nt][j] = 0.f;

    float4 pa[4], pb[NB];
    auto ldAB = [&](int kb) {
        #pragma unroll
        for (int i = 0; i < 4; i++) {
            int id = t + 256 * i, r = id >> 3, c4 = id & 7;
            pa[i] = *(const float4*)(Abase + (size_t)r * K + kb * 32 + c4 * 4);
        }
        #pragma unroll
        for (int i = 0; i < NB; i++) {
            int id = t + 256 * i, r = id >> 3, c4 = id & 7;
            pb[i] = *(const float4*)(Bbase + (size_t)r * K + kb * 32 + c4 * 4);
        }
    };
    auto stAB = [&](int buf) {
        uint16_t* bAh = sm + buf * BUFE;
        uint16_t* bAl = bAh + ASZ;
        uint16_t* bBh = bAl + ASZ;
        uint16_t* bBl = bBh + BSZ;
        #pragma unroll
        for (int i = 0; i < 4; i++) {
            int id = t + 256 * i, r = id >> 3, c4 = id & 7;
            uint2 hi, lo; split4(pa[i], hi, lo);
            *(uint2*)&bAh[r * 40 + c4 * 4] = hi;
            *(uint2*)&bAl[r * 40 + c4 * 4] = lo;
        }
        #pragma unroll
        for (int i = 0; i < NB; i++) {
            int id = t + 256 * i, r = id >> 3, c4 = id & 7;
            uint2 hi, lo; split4(pb[i], hi, lo);
            *(uint2*)&bBh[r * 40 + c4 * 4] = hi;
            *(uint2*)&bBl[r * 40 + c4 * 4] = lo;
        }
    };
    auto domma = [&](int buf) {
        const uint16_t* bAh = sm + buf * BUFE;
        const uint16_t* bAl = bAh + ASZ;
        const uint16_t* bBh = bAl + ASZ;
        const uint16_t* bBl = bBh + BSZ;
        #pragma unroll
        for (int ks = 0; ks < 2; ks++) {
            int kc = ks * 16 + tg * 2;
            uint32_t ah[2][4], al_[2][4];
            #pragma unroll
            for (int mt = 0; mt < 2; mt++) {
                int row = wm + mt * 16 + g;
                ah[mt][0]  = *(const uint32_t*)&bAh[row * 40 + kc];
                ah[mt][1]  = *(const uint32_t*)&bAh[(row + 8) * 40 + kc];
                ah[mt][2]  = *(const uint32_t*)&bAh[row * 40 + kc + 8];
                ah[mt][3]  = *(const uint32_t*)&bAh[(row + 8) * 40 + kc + 8];
                al_[mt][0] = *(const uint32_t*)&bAl[row * 40 + kc];
                al_[mt][1] = *(const uint32_t*)&bAl[(row + 8) * 40 + kc];
                al_[mt][2] = *(const uint32_t*)&bAl[row * 40 + kc + 8];
                al_[mt][3] = *(const uint32_t*)&bAl[(row + 8) * 40 + kc + 8];
            }
            #pragma unroll
            for (int nt = 0; nt < NT; nt++) {
                int col = wn + nt * 8 + g;
                uint32_t bh0 = *(const uint32_t*)&bBh[col * 40 + kc];
                uint32_t bh1 = *(const uint32_t*)&bBh[col * 40 + kc + 8];
                uint32_t bl0 = *(const uint32_t*)&bBl[col * 40 + kc];
                uint32_t bl1 = *(const uint32_t*)&bBl[col * 40 + kc + 8];
                #pragma unroll
                for (int mt = 0; mt < 2; mt++) {
                    mma16816(acc[mt][nt], ah[mt],  bh0, bh1);
                    mma16816(acc[mt][nt], al_[mt], bh0, bh1);
                    mma16816(acc[mt][nt], ah[mt],  bl0, bl1);
                }
            }
        }
    };

    int nkb = K >> 5;
    ldAB(0);
    stAB(0);
    __syncthreads();
    for (int kb = 0; kb < nkb; kb++) {
        int cur = kb & 1;
        if (kb + 1 < nkb) ldAB(kb + 1);
        domma(cur);
        if (kb + 1 < nkb) stAB(cur ^ 1);
        __syncthreads();
    }

    #pragma unroll
    for (int mt = 0; mt < 2; mt++) {
        size_t row = m0 + wm + mt * 16 + g;
        #pragma unroll
        for (int nt = 0; nt < NT; nt++) {
            size_t col = n0 + wn + nt * 8 + tg * 2;
            *(float2*)(C + row * ldc + col)       = make_float2(acc[mt][nt][0], acc[mt][nt][1]);
            *(float2*)(C + (row + 8) * ldc + col) = make_float2(acc[mt][nt][2], acc[mt][nt][3]);
        }
    }
}

// ---------------- weight packing ----------------
__global__ void pack2d(const float* __restrict__ src, float* __restrict__ dst, int Kd, int Cc) {
    int id = blockIdx.x * 256 + threadIdx.x;
    if (id < Kd * Cc) { int c = id % Cc, k = id / Cc; dst[c * Kd + k] = src[id]; }
}
__global__ void pack_hdp(const float* __restrict__ src, float* __restrict__ dst) {
    int id = blockIdx.x * 256 + threadIdx.x;
    if (id < Hh * Dd * PHp) {
        int p = id % PHp, d = (id / PHp) % Dd, h = id / (PHp * Dd);
        dst[(h * PHp + p) * Dd + d] = src[id];
    }
}

// ---------------- foldW (K=64): Wc[c,j] = sum_d Wep[j,d] * BtW[c,d] ----------------
__global__ __launch_bounds__(256) void foldW(const float* __restrict__ Wep,
                                             const float* __restrict__ BtW,
                                             float* __restrict__ Wc)
{
    __shared__ float sB[4][256];
    int t = threadIdx.x;
    int c0 = blockIdx.x * 4;
    for (int i = t; i < 4 * 256; i += 256)
        sB[i >> 8][i & 255] = BtW[(size_t)(c0 + (i >> 8)) * 256 + (i & 255)];
    __syncthreads();
    int cl = t >> 6, j = t & 63;
    const float* wr = Wep + (size_t)j * 256;
    float acc = 0.f;
    #pragma unroll 8
    for (int d = 0; d < 256; d++) acc += wr[d] * sB[cl][d];
    Wc[(size_t)(c0 + cl) * 64 + j] = acc;
}

// ---------------- foldW256: Wf[c,d] = sum_d' WpT[d',d] * BtW[c,d'] (Bt layout out, K=256) ----------------
__global__ __launch_bounds__(256) void foldW256(const float* __restrict__ WpT,
                                                const float* __restrict__ BtW,
                                                float* __restrict__ Wf)
{
    __shared__ float sb[256];
    int c = blockIdx.x, d = threadIdx.x;
    sb[d] = BtW[(size_t)c * 256 + d];
    __syncthreads();
    float acc = 0.f;
    #pragma unroll 4
    for (int dp = 0; dp < 256; dp++) acc += WpT[(size_t)dp * 256 + d] * sb[dp];
    Wf[(size_t)c * 256 + d] = acc;
}

// ---------------- foldA256: af[h,d] = sum_d' WpT[d',d] * a[h,d'] ----------------
__global__ __launch_bounds__(256) void foldA256(const float* __restrict__ WpT,
                                                const float* __restrict__ a,
                                                float* __restrict__ outp)
{
    __shared__ float sa[256];
    int h = blockIdx.x, d = threadIdx.x;
    sa[d] = a[(size_t)h * 256 + d];
    __syncthreads();
    float acc = 0.f;
    #pragma unroll 4
    for (int dp = 0; dp < 256; dp++) acc += WpT[(size_t)dp * 256 + d] * sa[dp];
    outp[(size_t)h * 256 + d] = acc;
}

// ---------------- foldA2 (K=64): out[s][h][j] = sum_d Wep[j,d]*a_s[h,d] ----------------
__global__ __launch_bounds__(256) void foldA2(const float* __restrict__ Wep,
                                              const float* __restrict__ a1,
                                              const float* __restrict__ a2,
                                              float* __restrict__ outp)
{
    __shared__ float s1[Hh * 256], s2[Hh * 256];
    int t = threadIdx.x;
    for (int i = t; i < Hh * 256; i += 256) { s1[i] = a1[i]; s2[i] = a2[i]; }
    __syncthreads();
    int h = t >> 6, j = t & 63;
    const float* wr = Wep + (size_t)j * 256;
    float A = 0.f, B = 0.f;
    #pragma unroll 8
    for (int d = 0; d < 256; d++) { float w = wr[d]; A += w * s1[h * 256 + d]; B += w * s2[h * 256 + d]; }
    outp[h * 64 + j] = A;
    outp[Hh * 64 + h * 64 + j] = B;
}

// ---------------- dual row-dot (D=256): one pass over X, two projection sets ----------------
__global__ __launch_bounds__(256) void rowdot2(const float* __restrict__ X,
                                               const float* __restrict__ avec1,
                                               const float* __restrict__ avec2,
                                               float* __restrict__ P1,
                                               float* __restrict__ P2)
{
    __shared__ float sa[2 * Hh * Dd];
    int t = threadIdx.x;
    for (int i = t; i < Hh * Dd; i += 256) { sa[i] = avec1[i]; sa[Hh * Dd + i] = avec2[i]; }
    __syncthreads();
    int row = blockIdx.x * 8 + (t >> 5);
    int lane = t & 31;
    const float* xr = X + (size_t)row * Dd;
    float a1[Hh] = {}, a2[Hh] = {};
    #pragma unroll
    for (int j = 0; j < 8; j++) {
        float xv = xr[lane + 32 * j];
        #pragma unroll
        for (int h = 0; h < Hh; h++) {
            a1[h] += sa[h * Dd + lane + 32 * j] * xv;
            a2[h] += sa[Hh * Dd + h * Dd + lane + 32 * j] * xv;
        }
    }
    #pragma unroll
    for (int h = 0; h < Hh; h++) {
        #pragma unroll
        for (int o = 16; o > 0; o >>= 1) {
            a1[h] += __shfl_down_sync(0xffffffffu, a1[h], o);
            a2[h] += __shfl_down_sync(0xffffffffu, a2[h], o);
        }
    }
    if (lane == 0) {
        #pragma unroll
        for (int h = 0; h < Hh; h++) {
            P1[(size_t)row * Hh + h] = a1[h];
            P2[(size_t)row * Hh + h] = a2[h];
        }
    }
}

// ---------------- single row-dot (D=256) ----------------
__global__ __launch_bounds__(256) void rowdot(const float* __restrict__ X,
                                              const float* __restrict__ avec,
                                              float* __restrict__ P, int M)
{
    __shared__ float sa[Hh * Dd];
    int t = threadIdx.x;
    for (int i = t; i < Hh * Dd; i += 256) sa[i] = avec[i];
    __syncthreads();
    int row = blockIdx.x * 8 + (t >> 5);
    int lane = t & 31;
    const float* xr = X + (size_t)row * Dd;
    float acc[Hh] = {};
    #pragma unroll
    for (int j = 0; j < 8; j++) {
        float xv = xr[lane + 32 * j];
        #pragma unroll
        for (int h = 0; h < Hh; h++) acc[h] += sa[h * Dd + lane + 32 * j] * xv;
    }
    #pragma unroll
    for (int h = 0; h < Hh; h++) {
        #pragma unroll
        for (int o = 16; o > 0; o >>= 1) acc[h] += __shfl_down_sync(0xffffffffu, acc[h], o);
    }
    if (lane == 0) {
        #pragma unroll
        for (int h = 0; h < Hh; h++) P[(size_t)row * Hh + h] = acc[h];
    }
}

// ---------------- dual row-dot over D=64 rows (edge_emb) ----------------
__global__ __launch_bounds__(256) void rowdot2_64(const float* __restrict__ X,
                                                  const float* __restrict__ avf,
                                                  float* __restrict__ P1,
                                                  float* __restrict__ P2)
{
    __shared__ float sa[2 * Hh * 64];
    int t = threadIdx.x;
    for (int i = t; i < 2 * Hh * 64; i += 256) sa[i] = avf[i];
    __syncthreads();
    int row = blockIdx.x * 8 + (t >> 5);
    int lane = t & 31;
    const float* xr = X + (size_t)row * 64;
    float x0 = xr[lane], x1 = xr[lane + 32];
    float a1[Hh], a2[Hh];
    #pragma unroll
    for (int h = 0; h < Hh; h++) {
        a1[h] = sa[h * 64 + lane] * x0 + sa[h * 64 + lane + 32] * x1;
        a2[h] = sa[256 + h * 64 + lane] * x0 + sa[256 + h * 64 + lane + 32] * x1;
    }
    #pragma unroll
    for (int h = 0; h < Hh; h++) {
        #pragma unroll
        for (int o = 16; o > 0; o >>= 1) {
            a1[h] += __shfl_down_sync(0xffffffffu, a1[h], o);
            a2[h] += __shfl_down_sync(0xffffffffu, a2[h], o);
        }
    }
    if (lane == 0) {
        #pragma unroll
        for (int h = 0; h < Hh; h++) {
            P1[(size_t)row * Hh + h] = a1[h];
            P2[(size_t)row * Hh + h] = a2[h];
        }
    }
}

__device__ __forceinline__ float elu1(float x) { return x > 0.f ? x : expm1f(x); }

// ---------------- edge combine + fused qe1 ----------------
__global__ __launch_bounds__(256) void edge_comb_q(const int* __restrict__ ena,
                                                   const float* __restrict__ pn,
                                                   const float* __restrict__ be,
                                                   const float* __restrict__ EW,
                                                   const float* __restrict__ Y,
                                                   const float* __restrict__ a1v,
                                                   float* __restrict__ eout,
                                                   float* __restrict__ qe1)
{
    __shared__ float sa1[Hh * Dd];
    __shared__ float sred[4][2][Hh];
    int t = threadIdx.x;
    for (int i = t; i < Hh * Dd; i += 256) sa1[i] = a1v[i];
    __syncthreads();

    int e0 = blockIdx.x * 4;
    int el = t >> 6, c4 = t & 63, h = c4 >> 4;
    int e = e0 + el;
    int u = ena[2 * e], v = ena[2 * e + 1];
    float b = be[(size_t)e * Hh + h];
    float s0 = pn[(size_t)u * Hh + h] + b;
    float s1 = pn[(size_t)v * Hh + h] + b;
    s0 = s0 > 0.f ? s0 : 0.2f * s0;
    s1 = s1 > 0.f ? s1 : 0.2f * s1;
    float m = fmaxf(s0, s1);
    float x0 = __expf(s0 - m), x1 = __expf(s1 - m);
    float inv = 1.f / (x0 + x1);
    float al0 = x0 * inv, al1 = x1 * inv;
    float4 ew = *(const float4*)(EW + (size_t)e * Dd + c4 * 4);
    float4 yu = *(const float4*)(Y + (size_t)u * Dd + c4 * 4);
    float4 yv = *(const float4*)(Y + (size_t)v * Dd + c4 * 4);
    float4 r;
    r.x = elu1(ew.x + al0 * yu.x + al1 * yv.x);
    r.y = elu1(ew.y + al0 * yu.y + al1 * yv.y);
    r.z = elu1(ew.z + al0 * yu.z + al1 * yv.z);
    r.w = elu1(ew.w + al0 * yu.w + al1 * yv.w);
    *(float4*)(eout + (size_t)e * Dd + c4 * 4) = r;

    float p[Hh];
    #pragma unroll
    for (int hh = 0; hh < Hh; hh++) {
        const float* av = sa1 + hh * Dd + c4 * 4;
        p[hh] = r.x * av[0] + r.y * av[1] + r.z * av[2] + r.w * av[3];
    }
    #pragma unroll
    for (int hh = 0; hh < Hh; hh++) {
        #pragma unroll
        for (int o = 16; o > 0; o >>= 1) p[hh] += __shfl_down_sync(0xffffffffu, p[hh], o);
    }
    int wl = t & 31, whalf = (t >> 5) & 1;
    if (wl == 0) {
        #pragma unroll
        for (int hh = 0; hh < Hh; hh++) sred[el][whalf][hh] = p[hh];
    }
    __syncthreads();
    if (t < 16) {
        int ee = t >> 2, hh = t & 3;
        qe1[(size_t)(e0 + ee) * Hh + hh] = sred[ee][0][hh] + sred[ee][1][hh];
    }
}

// ---------------- L0 node agg, projected ----------------
__global__ __launch_bounds__(256) void nagp_kernel(const int* __restrict__ n2e,
                                                   const float* __restrict__ ps,
                                                   const float* __restrict__ qe,
                                                   const float* __restrict__ EWnb,
                                                   float* __restrict__ NP)
{
    int t = threadIdx.x, w = t >> 5, lane = t & 31;
    int n = blockIdx.x * 8 + w;
    int idx[Kk];
    #pragma unroll
    for (int k = 0; k < Kk; k++) idx[k] = n2e[(size_t)n * Kk + k];
    float al[Hh][Kk];
    #pragma unroll
    for (int h = 0; h < Hh; h++) {
        float bs = ps[(size_t)n * Hh + h];
        float s[Kk]; float m = -1e30f;
        #pragma unroll
        for (int k = 0; k < Kk; k++) {
            float sv = bs + qe[(size_t)idx[k] * Hh + h];
            sv = sv > 0.f ? sv : 0.2f * sv;
            s[k] = sv; m = fmaxf(m, sv);
        }
        float sum = 0.f;
        #pragma unroll
        for (int k = 0; k < Kk; k++) { s[k] = __expf(s[k] - m); sum += s[k]; }
        float inv = 1.f / sum;
        #pragma unroll
        for (int k = 0; k < Kk; k++) al[h][k] = s[k] * inv;
    }
    int h0 = lane >> 4, h1 = 2 + (lane >> 4);
    float4 a0 = make_float4(0.f, 0.f, 0.f, 0.f), a1 = a0;
    #pragma unroll
    for (int k = 0; k < Kk; k++) {
        const float4* er = (const float4*)(EWnb + (size_t)idx[k] * Dd);
        float4 ea = er[lane], eb = er[32 + lane];
        float w0 = al[h0][k], w1 = al[h1][k];
        a0.x += w0 * ea.x; a0.y += w0 * ea.y; a0.z += w0 * ea.z; a0.w += w0 * ea.w;
        a1.x += w1 * eb.x; a1.y += w1 * eb.y; a1.z += w1 * eb.z; a1.w += w1 * eb.w;
    }
    *(float4*)(NP + (size_t)n * Dd + lane * 4)       = a0;
    *(float4*)(NP + (size_t)n * Dd + 128 + lane * 4) = a1;
}

// ---------------- L1 node aggregation (full) ----------------
__global__ __launch_bounds__(256) void nag_kernel(const int* __restrict__ n2e,
                                                  const float* __restrict__ ps,
                                                  const float* __restrict__ qe,
                                                  const float* __restrict__ edges,
                                                  float* __restrict__ nag)
{
    int t = threadIdx.x, w = t >> 5, lane = t & 31;
    int n = blockIdx.x * 8 + w;
    int idx[Kk];
    #pragma unroll
    for (int k = 0; k < Kk; k++) idx[k] = n2e[(size_t)n * Kk + k];
    float al[Hh][Kk];
    #pragma unroll
    for (int h = 0; h < Hh; h++) {
        float bs = ps[(size_t)n * Hh + h];
        float s[Kk]; float m = -1e30f;
        #pragma unroll
        for (int k = 0; k < Kk; k++) {
            float sv = bs + qe[(size_t)idx[k] * Hh + h];
            sv = sv > 0.f ? sv : 0.2f * sv;
            s[k] = sv; m = fmaxf(m, sv);
        }
        float sum = 0.f;
        #pragma unroll
        for (int k = 0; k < Kk; k++) { s[k] = __expf(s[k] - m); sum += s[k]; }
        float inv = 1.f / sum;
        #pragma unroll
        for (int k = 0; k < Kk; k++) al[h][k] = s[k] * inv;
    }
    float4 a0[Hh] = {}, a1[Hh] = {};
    #pragma unroll
    for (int k = 0; k < Kk; k++) {
        const float4* er = (const float4*)(edges + (size_t)idx[k] * Dd);
        float4 ea = er[lane], eb = er[32 + lane];
        #pragma unroll
        for (int h = 0; h < Hh; h++) {
            float a = al[h][k];
            a0[h].x += a * ea.x; a0[h].y += a * ea.y; a0[h].z += a * ea.z; a0[h].w += a * ea.w;
            a1[h].x += a * eb.x; a1[h].y += a * eb.y; a1[h].z += a * eb.z; a1[h].w += a * eb.w;
        }
    }
    #pragma unroll
    for (int h = 0; h < Hh; h++) {
        float* dst = nag + ((size_t)h * Nn + n) * Dd;
        *(float4*)(dst + lane * 4) = a0[h];
        *(float4*)(dst + 128 + lane * 4) = a1[h];
    }
}

// ---------------- node combine (L0) + fused ps_L1: xout = elu(S+NP); ps = xout . a_s1 ----------------
__global__ __launch_bounds__(256) void node_comb_ps(const float* __restrict__ S,
                                                    const float* __restrict__ NP,
                                                    const float* __restrict__ a1v,
                                                    float* __restrict__ out,
                                                    float* __restrict__ xout,
                                                    float* __restrict__ ps)
{
    __shared__ float sa1[Hh * Dd];
    __shared__ float sred[4][2][Hh];
    int t = threadIdx.x;
    for (int i = t; i < Hh * Dd; i += 256) sa1[i] = a1v[i];
    __syncthreads();

    int el = t >> 6, c4 = t & 63;
    int n = blockIdx.x * 4 + el;
    float4 s = *(const float4*)(S + (size_t)n * Dd + c4 * 4);
    float4 p = *(const float4*)(NP + (size_t)n * Dd + c4 * 4);
    float4 r;
    r.x = elu1(s.x + p.x); r.y = elu1(s.y + p.y);
    r.z = elu1(s.z + p.z); r.w = elu1(s.w + p.w);
    *(float4*)(out + (size_t)n * (DEPTHc * Dd) + c4 * 4) = r;
    *(float4*)(xout + (size_t)n * Dd + c4 * 4) = r;

    float pv[Hh];
    #pragma unroll
    for (int hh = 0; hh < Hh; hh++) {
        const float* av = sa1 + hh * Dd + c4 * 4;
        pv[hh] = r.x * av[0] + r.y * av[1] + r.z * av[2] + r.w * av[3];
    }
    #pragma unroll
    for (int hh = 0; hh < Hh; hh++) {
        #pragma unroll
        for (int o = 16; o > 0; o >>= 1) pv[hh] += __shfl_down_sync(0xffffffffu, pv[hh], o);
    }
    int wl = t & 31, whalf = (t >> 5) & 1;
    if (wl == 0) {
        #pragma unroll
        for (int hh = 0; hh < Hh; hh++) sred[el][whalf][hh] = pv[hh];
    }
    __syncthreads();
    if (t < 16) {
        int ee = t >> 2, hh = t & 3;
        ps[(size_t)(blockIdx.x * 4 + ee) * Hh + hh] = sred[ee][0][hh] + sred[ee][1][hh];
    }
}

// ---------------- node combine (L1) ----------------
__global__ __launch_bounds__(256) void node_comb(const float* __restrict__ S,
                                                 const float* __restrict__ NP,
                                                 float* __restrict__ out,
                                                 int Lofs)
{
    int gid = blockIdx.x * 256 + threadIdx.x;
    int n = gid >> 6, c4 = gid & 63;
    float4 s = *(const float4*)(S + (size_t)n * Dd + c4 * 4);
    float4 p = *(const float4*)(NP + (size_t)n * Dd + c4 * 4);
    float4 r;
    r.x = elu1(s.x + p.x); r.y = elu1(s.y + p.y);
    r.z = elu1(s.z + p.z); r.w = elu1(s.w + p.w);
    *(float4*)(out + (size_t)n * (DEPTHc * Dd) + Lofs + c4 * 4) = r;
}

// ---------------- launcher ----------------
extern "C" void kernel_launch(void* const* d_in, const int* in_sizes, int n_in,
                              void* d_out, int out_size)
{
    (void)in_sizes; (void)n_in; (void)out_size;
    const float* feats    = (const float*)d_in[0];
    const float* edge_emb = (const float*)d_in[1];
    const int*   ena      = (const int*)d_in[2];
    const int*   n2e      = (const int*)d_in[3];
    const float* Wp0      = (const float*)d_in[4];
    const float* Wp1      = (const float*)d_in[5];
    const float* Wep      = (const float*)d_in[6];
    const float* a_e      = (const float*)d_in[7];
    const float* a_n      = (const float*)d_in[8];
    const float* W_e      = (const float*)d_in[9];
    const float* a_s      = (const float*)d_in[10];
    const float* a_edge   = (const float*)d_in[11];
    const float* W_self   = (const float*)d_in[12];
    const float* W_nb     = (const float*)d_in[13];
    float* out = (float*)d_out;

    float *xb, *YS, *NP, *EW2, *eB, *nag, *pn, *be, *ps, *qe;
    float *WpT, *Bt0, *Bt1, *Bt2, *WfYS, *Wc, *avf, *av256;
    cudaGetSymbolAddress((void**)&xb,    g_x);
    cudaGetSymbolAddress((void**)&YS,    g_YS);
    cudaGetSymbolAddress((void**)&NP,    g_NP);
    cudaGetSymbolAddress((void**)&EW2,   g_EW2);
    cudaGetSymbolAddress((void**)&eB,    g_eB);
    cudaGetSymbolAddress((void**)&nag,   g_nag);
    cudaGetSymbolAddress((void**)&pn,    g_pn);
    cudaGetSymbolAddress((void**)&be,    g_be);
    cudaGetSymbolAddress((void**)&ps,    g_ps);
    cudaGetSymbolAddress((void**)&qe,    g_qe);
    cudaGetSymbolAddress((void**)&WpT,   g_WpT);
    cudaGetSymbolAddress((void**)&Bt0,   g_Bt0);
    cudaGetSymbolAddress((void**)&Bt1,   g_Bt1);
    cudaGetSymbolAddress((void**)&Bt2,   g_Bt2);
    cudaGetSymbolAddress((void**)&WfYS,  g_WfYS);
    cudaGetSymbolAddress((void**)&Wc,    g_Wc);
    cudaGetSymbolAddress((void**)&avf,   g_avf);
    cudaGetSymbolAddress((void**)&av256, g_av256);
    float* Y     = YS;
    float* S     = YS + (size_t)Nn * Dd;
    float* EW    = EW2;
    float* EWnb0 = EW2 + (size_t)Ee * Dd;
    float* WpT0  = WpT;
    float* WpT1  = WpT + Dd * Dd;

    constexpr int SM128 = 2 * (2 * 128 * 40 + 2 * 128 * 40) * 2; // 81920 B
    constexpr int SM64  = 2 * (2 * 128 * 40 + 2 * 64 * 40) * 2;  // 61440 B
    cudaFuncSetAttribute(gemm_mma<128>, cudaFuncAttributeMaxDynamicSharedMemorySize, SM128);
    cudaFuncSetAttribute(gemm_mma<64>,  cudaFuncAttributeMaxDynamicSharedMemorySize, SM64);

    dim3 blk(256);
    dim3 gN(Nn / 128, 2);         // N-rows, 256 cols
    dim3 gE2(Ee / 128, 2, 2);     // E-rows, 256 cols, z=2 (EW + EWnb0)
    dim3 gYS(Nn / 128, 2, 2);     // N-rows, z=2 (Y + S), A=feats shared
    dim3 gH(Nn / 128, 1, Hh);     // per-head GEMMs z-batched

    // hoisted: transposes of Wp0/Wp1
    pack2d<<<256, blk>>>(Wp0, WpT0, Dd, Dd);
    pack2d<<<256, blk>>>(Wp1, WpT1, Dd, Dd);

    for (int mp = 0; mp < NMPc; mp++) {
        const int*   ena_mp = ena + (size_t)mp * Ee * 2;
        const int*   n2e_mp = n2e + (size_t)mp * Nn * Kk;
        const float* emb_mp = edge_emb + (size_t)mp * Ee * EDd;
        const float* Wep_mp = Wep + (size_t)mp * EDd * Dd;
        float* outmp = out + (size_t)mp * Nn * DEPTHc * Dd;
        size_t pl0 = (size_t)(mp * DEPTHc + 0);
        size_t pl1 = (size_t)(mp * DEPTHc + 1);

        // ---- folds ----
        pack_hdp<<<256, blk>>>(W_e  + pl0 * Hh * Dd * PHp, Bt0);   // W_e(L0) Bt layout
        pack_hdp<<<256, blk>>>(W_nb + pl0 * Hh * Dd * PHp, Bt2);   // W_nb(L0)
        pack_hdp<<<256, blk>>>(W_self + pl0 * Hh * Dd * PHp, Bt1); // W_self(L0)
        foldW<<<64, blk>>>(Wep_mp, Bt0, Wc);                        // Wep@W_e   (K=64 panel)
        foldW<<<64, blk>>>(Wep_mp, Bt2, Wc + Dd * EDd);             // Wep@W_nb
        foldA2<<<1, blk>>>(Wep_mp, a_e + pl0 * Hh * Dd, a_edge + pl0 * Hh * Dd, avf);
        foldW256<<<256, blk>>>(WpT1, Bt0, WfYS);                    // WfY = Wp1-fold of W_e
        foldW256<<<256, blk>>>(WpT0, Bt1, WfYS + Dd * Dd);          // WfS = Wp0-fold of W_self
        foldA256<<<Hh, blk>>>(WpT1, a_n + pl0 * Hh * Dd, av256);            // pn vec
        foldA256<<<Hh, blk>>>(WpT0, a_s + pl0 * Hh * Dd, av256 + Hh * Dd);  // ps_L0 vec

        // ---- GEMMs ----
        gemm_mma<128><<<gE2, blk, SM128>>>(emb_mp, Wc, EW2, EDd, Dd,
                                           0, (size_t)Dd * EDd, (size_t)Ee * Dd);
        gemm_mma<128><<<gYS, blk, SM128>>>(feats, WfYS, YS, Dd, Dd,
                                           0, (size_t)Dd * Dd, (size_t)Nn * Dd);

        // ---- attention logits ----
        rowdot2<<<Nn / 8, blk>>>(feats, av256, av256 + Hh * Dd, pn, ps);  // pn, ps_L0
        rowdot2_64<<<Ee / 8, blk>>>(emb_mp, avf, be, qe);                  // be, qe0

        // ---- edge combine (+ fused qe1 into g_be) ----
        edge_comb_q<<<Ee / 4, blk>>>(ena_mp, pn, be, EW, Y,
                                     a_edge + pl1 * Hh * Dd, eB, be);

        // ---- layer 0 node aggregator (projected path) ----
        nagp_kernel<<<Nn / 8, blk>>>(n2e_mp, ps, qe, EWnb0, NP);
        node_comb_ps<<<Nn / 4, blk>>>(S, NP, a_s + pl1 * Hh * Dd, outmp, xb, ps); // + ps_L1

        // ---- layer 1 node aggregator ----
        nag_kernel<<<Nn / 8, blk>>>(n2e_mp, ps, be, eB, nag);   // be holds qe1
        pack_hdp<<<256, blk>>>(W_nb + pl1 * Hh * Dd * PHp, Bt2);
        gemm_mma<64><<<gH, blk, SM64>>>(nag, Bt2, NP, Dd, Dd,
                                        (size_t)Nn * Dd, (size_t)PHp * Dd, (size_t)PHp);
        pack_hdp<<<256, blk>>>(W_self + pl1 * Hh * Dd * PHp, Bt1);
        gemm_mma<128><<<gN, blk, SM128>>>(xb, Bt1, S, Dd, Dd, 0, 0, 0);
        node_comb<<<Nn * 64 / 256, blk>>>(S, NP, outmp, Dd);
    }
}